// round 15
// baseline (speedup 1.0000x reference)
#include <cuda_runtime.h>
#include <cuda_bf16.h>
#include <cstdint>
#include <math.h>

#define V_ 10000
#define T_ 100
#define K_ 50
#define R_ 300
#define H_ 200
#define EN_ 800
#define B_ 128
#define TK_ 5000
#define VKP_ 10056
#define COEFF 781.25
// beta MMA tiling
#define KP 320
#define MP 5120
#define NP 10240
typedef unsigned long long ull;

// ---------------- static device scratch (allocation-free) ----------------
__device__ __align__(16) float g_E[(size_t)TK_ * V_];     // exp(logits), 200MB
__device__ float  g_Z[TK_];                                // softmax denominators
__device__ double g_acc[4];                                // nll, kl_eta, kl_theta, kl_alpha (raw)
__device__ int    g_flag[3][T_][8];                        // pipeline flags
__device__ __align__(16) float g_x[T_ * H_];               // eta_map output (layer0 input)
__device__ __align__(16) float g_gates0[T_ * 4 * H_];      // precomputed layer0 input gates
__device__ __align__(16) float g_seq3[3][T_ * H_];         // per-layer LSTM outputs
__device__ float  g_etas[T_ * K_];
__device__ __align__(16) float g_enc[(size_t)B_ * VKP_];
__device__ __align__(16) float g_h1[B_ * EN_];
__device__ __align__(16) float g_h2[B_ * EN_];
__device__ float  g_w[B_ * K_];
__device__ __align__(16) float g_w1p[(size_t)EN_ * VKP_];
__device__ __align__(16) __nv_bfloat16 g_aTh[(size_t)MP * KP];  // alphas bf16 [MP,KP]
__device__ __align__(16) __nv_bfloat16 g_rhh[(size_t)NP * KP];  // rho bf16 [NP,KP]
__device__ __align__(16) float g_part[(size_t)63 * B_ * EN_];   // split-K partial slabs (25.8MB)

#define WSTRIDE 204
#define REC_SMEM ((2 * 100 * WSTRIDE + 2 * WSTRIDE + 200 + 100 + 100 + 64) * 4)

__device__ __forceinline__ float exp_acc(float x) { return (float)exp((double)x); }

// plain float4 dot over 200 floats (both 16B-aligned); compiler pipelines LDS
__device__ __forceinline__ float dot200(const float* __restrict__ w, const float* __restrict__ v) {
    const float4* w4 = (const float4*)w;
    const float4* v4 = (const float4*)v;
    float a0 = 0.f, a1 = 0.f, a2 = 0.f, a3 = 0.f;
#pragma unroll
    for (int q = 0; q < 50; q++) {
        float4 a = w4[q], b = v4[q];
        a0 += a.x * b.x; a1 += a.y * b.y; a2 += a.z * b.z; a3 += a.w * b.w;
    }
    return (a0 + a1) + (a2 + a3);
}

// ---------------- init / prep ----------------
__global__ void k_init() {
    int i0 = blockIdx.x * blockDim.x + threadIdx.x;
    int st = gridDim.x * blockDim.x;
    for (int i = i0; i < TK_; i += st) g_Z[i] = 0.f;
    for (int i = i0; i < 3 * T_ * 8; i += st) ((int*)g_flag)[i] = 0;
    if (i0 < 4) g_acc[i0] = 0.0;
}

// bf16 beta operands (zero-padded)
__global__ void k_prep_beta(const float* __restrict__ rho, const float* __restrict__ mua) {
    size_t i0 = (size_t)blockIdx.x * blockDim.x + threadIdx.x;
    size_t st = (size_t)gridDim.x * blockDim.x;
    for (size_t i = i0; i < (size_t)NP * KP; i += st) {
        int n = (int)(i / KP), k = (int)(i % KP);
        g_rhh[i] = (n < V_ && k < R_) ? __float2bfloat16(rho[(size_t)n * R_ + k]) : __float2bfloat16(0.f);
    }
    for (size_t i = i0; i < (size_t)MP * KP; i += st) {
        int m = (int)(i / KP), r = (int)(i % KP);
        int t = m / K_, kk = m % K_;
        g_aTh[i] = (m < TK_ && r < R_) ? __float2bfloat16(mua[((size_t)kk * T_ + t) * R_ + r])
                                       : __float2bfloat16(0.f);
    }
}

__global__ void k_prep_w1(const float* __restrict__ qW1) {
    size_t i0 = (size_t)blockIdx.x * blockDim.x + threadIdx.x;
    size_t st = (size_t)gridDim.x * blockDim.x;
    for (size_t i = i0; i < (size_t)EN_ * VKP_; i += st) {
        int e = (int)(i / VKP_), j = (int)(i % VKP_);
        g_w1p[i] = (j < V_ + K_) ? qW1[(size_t)e * (V_ + K_) + j] : 0.f;
    }
}

// ---------------- beta via mma.sync bf16 (HMMA): E = exp(A@B^T), Z row sums ----------------
__global__ __launch_bounds__(256) void beta_mma(
    const __nv_bfloat16* __restrict__ Ah, const __nv_bfloat16* __restrict__ Bh,
    float* __restrict__ E, float* __restrict__ Zr)
{
    __shared__ __align__(16) uint32_t sA[128 * 20];
    __shared__ __align__(16) uint32_t sB[128 * 20];
    __shared__ float zs[128];

    int tid = threadIdx.x;
    int lane = tid & 31, wid = tid >> 5;
    int mw = wid >> 1, nw = wid & 1;
    int gr = lane >> 2, cl = lane & 3;
    int m0 = blockIdx.y * 128, n0 = blockIdx.x * 128;

    float c[2][8][4];
#pragma unroll
    for (int mi = 0; mi < 2; mi++)
#pragma unroll
        for (int ni = 0; ni < 8; ni++)
#pragma unroll
            for (int q = 0; q < 4; q++) c[mi][ni][q] = 0.f;

    if (tid < 128) zs[tid] = 0.f;

    int lrow = tid >> 1;
    int lkk = (tid & 1) * 16;

    for (int ch = 0; ch < 10; ch++) {
        const __nv_bfloat16* Ap = Ah + (size_t)(m0 + lrow) * KP + ch * 32 + lkk;
        const __nv_bfloat16* Bp = Bh + (size_t)(n0 + lrow) * KP + ch * 32 + lkk;
        float4 av0 = *(const float4*)Ap;
        float4 av1 = *(const float4*)(Ap + 8);
        float4 bv0 = *(const float4*)Bp;
        float4 bv1 = *(const float4*)(Bp + 8);
        __syncthreads();
        *(float4*)&sA[lrow * 20 + (lkk >> 1)]     = av0;
        *(float4*)&sA[lrow * 20 + (lkk >> 1) + 4] = av1;
        *(float4*)&sB[lrow * 20 + (lkk >> 1)]     = bv0;
        *(float4*)&sB[lrow * 20 + (lkk >> 1) + 4] = bv1;
        __syncthreads();
#pragma unroll
        for (int ks = 0; ks < 2; ks++) {
            int kw = ks * 8;
            uint32_t af[2][4];
#pragma unroll
            for (int mi = 0; mi < 2; mi++) {
                int r0 = mw * 32 + mi * 16 + gr;
                af[mi][0] = sA[r0 * 20 + kw + cl];
                af[mi][1] = sA[(r0 + 8) * 20 + kw + cl];
                af[mi][2] = sA[r0 * 20 + kw + cl + 4];
                af[mi][3] = sA[(r0 + 8) * 20 + kw + cl + 4];
            }
#pragma unroll
            for (int ni = 0; ni < 8; ni++) {
                int nr = nw * 64 + ni * 8 + gr;
                uint32_t b0 = sB[nr * 20 + kw + cl];
                uint32_t b1 = sB[nr * 20 + kw + cl + 4];
#pragma unroll
                for (int mi = 0; mi < 2; mi++) {
                    asm volatile(
                        "mma.sync.aligned.m16n8k16.row.col.f32.bf16.bf16.f32 "
                        "{%0,%1,%2,%3}, {%4,%5,%6,%7}, {%8,%9}, {%0,%1,%2,%3};"
                        : "+f"(c[mi][ni][0]), "+f"(c[mi][ni][1]),
                          "+f"(c[mi][ni][2]), "+f"(c[mi][ni][3])
                        : "r"(af[mi][0]), "r"(af[mi][1]), "r"(af[mi][2]), "r"(af[mi][3]),
                          "r"(b0), "r"(b1));
                }
            }
        }
    }

#pragma unroll
    for (int mi = 0; mi < 2; mi++) {
        int lr0 = mw * 32 + mi * 16 + gr;
        int lr1 = lr0 + 8;
        int grow0 = m0 + lr0, grow1 = m0 + lr1;
        float z0 = 0.f, z1 = 0.f;
#pragma unroll
        for (int ni = 0; ni < 8; ni++) {
            int col = n0 + nw * 64 + ni * 8 + cl * 2;
            float e0 = expf(c[mi][ni][0]);
            float e1 = expf(c[mi][ni][1]);
            float e2 = expf(c[mi][ni][2]);
            float e3 = expf(c[mi][ni][3]);
            bool c0ok = col < V_, c1ok = col + 1 < V_;
            if (grow0 < TK_) {
                if (c1ok)      *(float2*)&E[(size_t)grow0 * V_ + col] = make_float2(e0, e1);
                else if (c0ok) E[(size_t)grow0 * V_ + col] = e0;
            }
            if (grow1 < TK_) {
                if (c1ok)      *(float2*)&E[(size_t)grow1 * V_ + col] = make_float2(e2, e3);
                else if (c0ok) E[(size_t)grow1 * V_ + col] = e2;
            }
            if (c0ok) { z0 += e0; z1 += e2; }
            if (c1ok) { z0 += e1; z1 += e3; }
        }
        z0 += __shfl_xor_sync(0xFFFFFFFF, z0, 1);
        z0 += __shfl_xor_sync(0xFFFFFFFF, z0, 2);
        z1 += __shfl_xor_sync(0xFFFFFFFF, z1, 1);
        z1 += __shfl_xor_sync(0xFFFFFFFF, z1, 2);
        if (cl == 0) {
            atomicAdd(&zs[lr0], z0);
            atomicAdd(&zs[lr1], z1);
        }
    }
    __syncthreads();
    if (tid < 128 && m0 + tid < TK_) atomicAdd(&Zr[m0 + tid], zs[tid]);
}

// ---------------- fused recurrent pipeline: 3 LSTM layers + eta scan ----------------
// CTAs 0..23: layer l = cta/8, slice s = cta%8 (25 states each).
// Layer 0 input gates precomputed (g_gates0). Layers 1-2 split wi/wh across 200 threads.
// CTA 24: eta scan. Flag-based sync (store -> fence -> sync -> atomicExch flag).
__global__ __launch_bounds__(256) void rec_pipeline(
    const float* __restrict__ gates0,
    const float* __restrict__ Wih, const float* __restrict__ Whh,
    const float* __restrict__ bih, const float* __restrict__ bhh,
    const float* __restrict__ Wm, const float* __restrict__ bm,
    const float* __restrict__ Wl, const float* __restrict__ bl,
    float* __restrict__ etas, double* acc)
{
    extern __shared__ float smf[];
    int cta = blockIdx.x, tid = threadIdx.x;

    if (cta < 24) {
        int l = cta >> 3, s = cta & 7;
        float* Wih_s = smf;                         // 100 x WSTRIDE (unused for l==0)
        float* Whh_s = smf + 100 * WSTRIDE;
        float* x_s   = smf + 2 * 100 * WSTRIDE;     // WSTRIDE
        float* h_s   = x_s + WSTRIDE;               // WSTRIDE
        float* pp    = h_s + WSTRIDE;               // 200 partials
        float* bias_s = pp + 200;                   // 100
        float* gb    = bias_s + 100;                // 100 (layer0)
        float* c_s   = gb + 100;                    // 25

        for (int i = tid; i < 100 * 200; i += 256) {
            int rl = i / 200, h = i % 200;
            int grow = (rl / 25) * 200 + s * 25 + (rl % 25);
            if (l > 0)
                Wih_s[rl * WSTRIDE + h] = Wih[(size_t)l * 800 * 200 + (size_t)grow * 200 + h];
            Whh_s[rl * WSTRIDE + h] = Whh[(size_t)l * 800 * 200 + (size_t)grow * 200 + h];
        }
        int myrow = -1, mygrow = 0;
        if (tid < 100) {
            myrow = tid;
            mygrow = (tid / 25) * 200 + s * 25 + (tid % 25);
            bias_s[tid] = bih[l * 800 + mygrow] + bhh[l * 800 + mygrow];
        }
        if (tid < 25) c_s[tid] = 0.f;
        if (tid < 200) { h_s[tid] = 0.f; x_s[tid] = 0.f; }
        __syncthreads();

        for (int t = 0; t < 100; t++) {
            float g0 = 0.f;
            if (l == 0 && tid < 100) g0 = gates0[t * 800 + mygrow];   // off-path prefetch
            // parallel waits: own layer t-1 (tid 0-7), prev layer t (tid 16-23)
            if (t > 0 && tid < 8) {
                volatile int* f = &g_flag[l][t - 1][tid];
                while (!*f) { }
                __threadfence();
            }
            if (l > 0 && tid >= 16 && tid < 24) {
                volatile int* f = &g_flag[l - 1][t][tid - 16];
                while (!*f) { }
                __threadfence();
            }
            __syncthreads();
            if (tid < 200) {
                if (l > 0) x_s[tid] = __ldcg(&g_seq3[l - 1][t * 200 + tid]);
                if (t > 0) h_s[tid] = __ldcg(&g_seq3[l][(t - 1) * 200 + tid]);
            }
            __syncthreads();
            if (l == 0) {
                if (tid < 100)
                    gb[tid] = dot200(&Whh_s[tid * WSTRIDE], h_s) + g0 + bias_s[tid];
            } else {
                if (tid < 100)
                    pp[tid] = dot200(&Wih_s[tid * WSTRIDE], x_s);
                else if (tid < 200)
                    pp[tid] = dot200(&Whh_s[(tid - 100) * WSTRIDE], h_s);
            }
            __syncthreads();
            if (tid < 25) {
                float vi, vf, vg, vo;
                if (l == 0) {
                    vi = gb[tid]; vf = gb[25 + tid]; vg = gb[50 + tid]; vo = gb[75 + tid];
                } else {
                    vi = pp[tid] + pp[100 + tid] + bias_s[tid];
                    vf = pp[25 + tid] + pp[125 + tid] + bias_s[25 + tid];
                    vg = pp[50 + tid] + pp[150 + tid] + bias_s[50 + tid];
                    vo = pp[75 + tid] + pp[175 + tid] + bias_s[75 + tid];
                }
                float ig = 1.f / (1.f + expf(-vi));
                float fg = 1.f / (1.f + expf(-vf));
                float gg = tanhf(vg);
                float og = 1.f / (1.f + expf(-vo));
                float c = fg * c_s[tid] + ig * gg;
                c_s[tid] = c;
                float hn = og * tanhf(c);
                __stcg(&g_seq3[l][t * 200 + s * 25 + tid], hn);
                __threadfence();
            }
            __syncthreads();
            if (tid == 0) atomicExch(&g_flag[l][t][s], 1);
        }
    } else {
        float* Wms = smf;
        float* Wls = Wms + 50 * 251;
        float* x_s = Wls + 50 * 251;
        float* mu_s = x_s + 256;
        float* ls_s = mu_s + 50;
        float* ep = ls_s + 50;
        double* dred = (double*)(ep + 50);
        for (int i = tid; i < 50 * 250; i += 256) {
            int r = i / 250, c = i % 250;
            Wms[r * 251 + c] = Wm[i];
            Wls[r * 251 + c] = Wl[i];
        }
        if (tid < 50) ep[tid] = 0.f;
        __syncthreads();
        const float LOGD = (float)log(0.005);
        const float DEN1 = 1.0f + 1e-6f;
        const float DEND = __fadd_rn(exp_acc(LOGD), 1e-6f);
        double kl = 0.0;
        for (int t = 0; t < 100; t++) {
            if (tid < 8) {
                volatile int* f = &g_flag[2][t][tid];
                while (!*f) { }
                __threadfence();
            }
            __syncthreads();
            if (tid < 200) x_s[tid] = __ldcg(&g_seq3[2][t * 200 + tid]);
            else if (tid < 250) x_s[tid] = ep[tid - 200];
            __syncthreads();
            if (tid < 50) {
                const float* w = &Wms[tid * 251];
                float a0 = 0.f, a1 = 0.f;
#pragma unroll 5
                for (int h = 0; h < 250; h += 2) { a0 += w[h] * x_s[h]; a1 += w[h + 1] * x_s[h + 1]; }
                mu_s[tid] = a0 + a1 + bm[tid];
            } else if (tid >= 64 && tid < 114) {
                int k = tid - 64;
                const float* w = &Wls[k * 251];
                float a0 = 0.f, a1 = 0.f;
#pragma unroll 5
                for (int h = 0; h < 250; h += 2) { a0 += w[h] * x_s[h]; a1 += w[h + 1] * x_s[h + 1]; }
                ls_s[k] = a0 + a1 + bl[k];
            }
            __syncthreads();
            if (tid < 50) {
                float mu = mu_s[tid], ls = ls_s[tid], pmu = ep[tid];
                float pls = (t == 0) ? 0.f : LOGD;
                float den = (t == 0) ? DEN1 : DEND;
                float d  = __fadd_rn(mu, -pmu);
                float d2 = __fmul_rn(d, d);
                float Ex = exp_acc(ls);
                float S  = __fadd_rn(Ex, d2);
                float Q  = __fdiv_rn(S, den);
                float t1 = __fadd_rn(Q, -1.0f);
                float t2 = __fadd_rn(t1, pls);
                kl += (double)__fadd_rn(t2, -ls);
                etas[t * 50 + tid] = mu;
                ep[tid] = mu;
            }
            __syncthreads();
        }
        if (tid < 64) {
            for (int o = 16; o > 0; o >>= 1)
                kl += __shfl_down_sync(0xFFFFFFFF, kl, o);
            if ((tid & 31) == 0) dred[tid >> 5] = kl;
        }
        __syncthreads();
        if (tid == 0) atomicAdd(&acc[1], 0.5 * (dred[0] + dred[1]));
    }
}

// ---------------- NT SGEMM, f32x2 FFMA, split-K -> partial slabs ----------------
__global__ __launch_bounds__(256) void gemm_nt(
    const float* __restrict__ A, const float* __restrict__ B,
    float* __restrict__ P, int M, int N, int K, int lda, int ldb)
{
    __shared__ __align__(16) float As[2][8][128];
    __shared__ __align__(16) float Bs[2][8][128];
    int tid = threadIdx.x, tx = tid & 15, ty = tid >> 4;
    int row0 = blockIdx.y * 128, col0 = blockIdx.x * 128;
    int nk = K >> 3;
    int cps = (nk + gridDim.z - 1) / gridDim.z;
    int kc0 = blockIdx.z * cps, kc1 = min(nk, kc0 + cps);
    float* Pz = P + (size_t)blockIdx.z * M * N;

    if (kc0 >= kc1) {
#pragma unroll
        for (int i = 0; i < 8; i++) {
            int m = row0 + ty * 8 + i;
            if (m >= M) continue;
#pragma unroll
            for (int j = 0; j < 8; j++) {
                int n = col0 + tx * 8 + j;
                if (n < N) Pz[(size_t)m * N + n] = 0.f;
            }
        }
        return;
    }

    ull acc[8][4];
#pragma unroll
    for (int i = 0; i < 8; i++)
#pragma unroll
        for (int j = 0; j < 4; j++) acc[i][j] = 0ULL;

    int arow = tid >> 1, akq = (tid & 1) << 2;
    const float* Ap = A + (size_t)(row0 + arow) * lda + akq;
    const float* Bp = B + (size_t)(col0 + arow) * ldb + akq;
    bool am = (row0 + arow) < M, bn = (col0 + arow) < N;
    {
        int kb = kc0 << 3;
        float4 va = make_float4(0.f, 0.f, 0.f, 0.f);
        float4 vb = make_float4(0.f, 0.f, 0.f, 0.f);
        if (am) va = *(const float4*)(Ap + kb);
        if (bn) vb = *(const float4*)(Bp + kb);
        As[0][akq + 0][arow] = va.x; As[0][akq + 1][arow] = va.y;
        As[0][akq + 2][arow] = va.z; As[0][akq + 3][arow] = va.w;
        Bs[0][akq + 0][arow] = vb.x; Bs[0][akq + 1][arow] = vb.y;
        Bs[0][akq + 2][arow] = vb.z; Bs[0][akq + 3][arow] = vb.w;
    }
    __syncthreads();
    for (int kc = kc0; kc < kc1; kc++) {
        int cur = (kc - kc0) & 1;
        bool more = (kc + 1 < kc1);
        float4 va2 = make_float4(0.f, 0.f, 0.f, 0.f);
        float4 vb2 = make_float4(0.f, 0.f, 0.f, 0.f);
        if (more) {
            int kb2 = (kc + 1) << 3;
            if (am) va2 = *(const float4*)(Ap + kb2);
            if (bn) vb2 = *(const float4*)(Bp + kb2);
        }
#pragma unroll
        for (int k = 0; k < 8; k++) {
            ull a2[8], b2[4];
            const ull* brow = (const ull*)&Bs[cur][k][0];
#pragma unroll
            for (int j = 0; j < 4; j++) b2[j] = brow[tx * 4 + j];
#pragma unroll
            for (int i = 0; i < 8; i++) {
                unsigned u = __float_as_uint(As[cur][k][ty * 8 + i]);
                asm("mov.b64 %0,{%1,%1};" : "=l"(a2[i]) : "r"(u));
            }
#pragma unroll
            for (int i = 0; i < 8; i++)
#pragma unroll
                for (int j = 0; j < 4; j++)
                    asm("fma.rn.f32x2 %0,%1,%2,%3;"
                        : "=l"(acc[i][j]) : "l"(a2[i]), "l"(b2[j]), "l"(acc[i][j]));
        }
        if (more) {
            int nxt = cur ^ 1;
            As[nxt][akq + 0][arow] = va2.x; As[nxt][akq + 1][arow] = va2.y;
            As[nxt][akq + 2][arow] = va2.z; As[nxt][akq + 3][arow] = va2.w;
            Bs[nxt][akq + 0][arow] = vb2.x; Bs[nxt][akq + 1][arow] = vb2.y;
            Bs[nxt][akq + 2][arow] = vb2.z; Bs[nxt][akq + 3][arow] = vb2.w;
        }
        __syncthreads();
    }
#pragma unroll
    for (int i = 0; i < 8; i++) {
        int m = row0 + ty * 8 + i;
        if (m >= M) continue;
#pragma unroll
        for (int j = 0; j < 4; j++) {
            int n = col0 + tx * 8 + 2 * j;
            float lo = __uint_as_float((unsigned)acc[i][j]);
            float hi = __uint_as_float((unsigned)(acc[i][j] >> 32));
            if (n < N) Pz[(size_t)m * N + n] = lo;
            if (n + 1 < N) Pz[(size_t)m * N + n + 1] = hi;
        }
    }
}

// ---------------- reduce partial slabs + optional bias (+relu) ----------------
__global__ void k_red(float* __restrict__ C, const float* __restrict__ P,
                      const float* __restrict__ b1, int M, int N, int nz, int relu) {
    int tot = M * N;
    size_t slab = (size_t)M * N;
    for (int i = blockIdx.x * blockDim.x + threadIdx.x; i < tot; i += gridDim.x * blockDim.x) {
        float v = b1 ? b1[i % N] : 0.f;
        for (int z = 0; z < nz; z++) v += P[(size_t)z * slab + i];
        if (relu) v = fmaxf(v, 0.f);
        C[i] = v;
    }
}

// ---------------- encoder input build: bows part (side stream) ----------------
__global__ void k_enc_bows(const float* __restrict__ bows, float* __restrict__ enc)
{
    __shared__ float red[256];
    __shared__ float inv;
    int b = blockIdx.x, tid = threadIdx.x;
    float s = 0.f;
    for (int v = tid; v < V_; v += 256) s += bows[(size_t)b * V_ + v];
    red[tid] = s; __syncthreads();
    for (int st = 128; st > 0; st >>= 1) { if (tid < st) red[tid] += red[tid + st]; __syncthreads(); }
    if (tid == 0) inv = 1.f / red[0];
    __syncthreads();
    for (int v = tid; v < V_; v += 256) enc[(size_t)b * VKP_ + v] = bows[(size_t)b * V_ + v] * inv;
    if (tid >= 50 && tid < 56) enc[(size_t)b * VKP_ + V_ + tid] = 0.f;
}

// ---------------- encoder input: eta columns (main, after rec) ----------------
__global__ void k_enc_eta(const int* __restrict__ times, const float* __restrict__ etas,
                          float* __restrict__ enc)
{
    int b = blockIdx.x, tid = threadIdx.x;
    int t = times[b];
    if (tid < 50) enc[(size_t)b * VKP_ + V_ + tid] = etas[t * 50 + tid];
}

// ---------------- theta head ----------------
__global__ __launch_bounds__(128) void k_theta(const float* __restrict__ h2,
    const float* __restrict__ Wm, const float* __restrict__ bm,
    const float* __restrict__ Wl, const float* __restrict__ bl,
    const int* __restrict__ times, const float* __restrict__ etas,
    const float* __restrict__ Z, float* __restrict__ w, double* acc)
{
    __shared__ float hs[800], mu[50], ls[50], term[50];
    __shared__ float mx, sz;
    int b = blockIdx.x, tid = threadIdx.x;
    for (int i = tid; i < 800; i += 128) hs[i] = h2[b * 800 + i];
    __syncthreads();
    if (tid < 50) {
        const float* wr = &Wm[tid * 800];
        float a0 = 0.f, a1 = 0.f;
        for (int e = 0; e < 800; e += 2) { a0 += wr[e] * hs[e]; a1 += wr[e + 1] * hs[e + 1]; }
        mu[tid] = a0 + a1 + bm[tid];
    } else if (tid >= 64 && tid < 114) {
        int k = tid - 64;
        const float* wr = &Wl[k * 800];
        float a0 = 0.f, a1 = 0.f;
        for (int e = 0; e < 800; e += 2) { a0 += wr[e] * hs[e]; a1 += wr[e + 1] * hs[e + 1]; }
        ls[k] = a0 + a1 + bl[k];
    }
    __syncthreads();
    if (tid == 0) {
        float m = mu[0];
        for (int k = 1; k < 50; k++) m = fmaxf(m, mu[k]);
        float s = 0.f;
        for (int k = 0; k < 50; k++) s += expf(mu[k] - m);
        mx = m; sz = s;
    }
    __syncthreads();
    int t = times[b];
    if (tid < 50) {
        float th = expf(mu[tid] - mx) / sz;
        w[b * 50 + tid] = th / Z[t * 50 + tid];
        float pmu = etas[t * 50 + tid];
        float d  = __fadd_rn(mu[tid], -pmu);
        float d2 = __fmul_rn(d, d);
        float Ex = exp_acc(ls[tid]);
        float S  = __fadd_rn(Ex, d2);
        float Q  = __fdiv_rn(S, 1.0f + 1e-6f);
        float t1 = __fadd_rn(Q, -1.0f);
        term[tid] = __fadd_rn(t1, -ls[tid]);
    }
    __syncthreads();
    if (tid == 0) {
        double s = 0.0;
        for (int k = 0; k < 50; k++) s += (double)term[k];
        atomicAdd(&acc[2], 0.5 * s);
    }
}

// ---------------- NLL ----------------
__global__ __launch_bounds__(256) void k_nll(const float* __restrict__ bows,
    const int* __restrict__ times, const float* __restrict__ w,
    const float* __restrict__ E, double* acc)
{
    __shared__ float ws[50];
    __shared__ double red[256];
    int b = blockIdx.y, tid = threadIdx.x;
    int v = blockIdx.x * 256 + tid;
    if (tid < 50) ws[tid] = w[b * 50 + tid];
    __syncthreads();
    double local = 0.0;
    if (v < V_) {
        const float* Eb = E + (size_t)(times[b] * 50) * V_ + v;
        float a = 0.f;
#pragma unroll 10
        for (int k = 0; k < 50; k++) a += ws[k] * Eb[(size_t)k * V_];
        local = -(double)logf(a + 1e-12f) * (double)bows[(size_t)b * V_ + v];
    }
    red[tid] = local; __syncthreads();
    for (int st = 128; st > 0; st >>= 1) { if (tid < st) red[tid] += red[tid + st]; __syncthreads(); }
    if (tid == 0) atomicAdd(&acc[0], red[0]);
}

// ---------------- alpha KL ----------------
__global__ __launch_bounds__(256) void k_alpha(const float* __restrict__ mua,
                                               const float* __restrict__ lsa, double* acc)
{
    __shared__ double red[256];
    const float LOGD = (float)log(0.005);
    const float DEN1 = 1.0f + 1e-6f;
    const float DEND = __fadd_rn(exp_acc(LOGD), 1e-6f);
    int tid = threadIdx.x;
    double local = 0.0;
    int tot = K_ * T_ * R_;
    for (int idx = blockIdx.x * 256 + tid; idx < tot; idx += gridDim.x * 256) {
        int t = (idx / R_) % T_;
        float mu = mua[idx], ls = lsa[idx];
        float pmu = (t == 0) ? 0.f : mua[idx - R_];
        float pls = (t == 0) ? 0.f : LOGD;
        float den = (t == 0) ? DEN1 : DEND;
        float d  = __fadd_rn(mu, -pmu);
        float d2 = __fmul_rn(d, d);
        float Ex = expf(ls);
        float S  = __fadd_rn(Ex, d2);
        float Q  = __fdiv_rn(S, den);
        float t1 = __fadd_rn(Q, -1.0f);
        float t2 = __fadd_rn(t1, pls);
        local += (double)__fadd_rn(t2, -ls);
    }
    red[tid] = local; __syncthreads();
    for (int st = 128; st > 0; st >>= 1) { if (tid < st) red[tid] += red[tid + st]; __syncthreads(); }
    if (tid == 0) atomicAdd(&acc[3], 0.5 * red[0]);
}

// ---------------- finalize ----------------
__global__ void k_final(float* out, const double* acc) {
    if (threadIdx.x == 0 && blockIdx.x == 0) {
        double nll = acc[0] * COEFF;
        double kle = acc[1];
        double klt = acc[2] * COEFF;
        double kla = acc[3];
        out[0] = (float)(nll + kle + klt + kla);
        out[1] = (float)nll;
        out[2] = (float)kle;
        out[3] = (float)klt;
        out[4] = (float)kla;
    }
}

// ---------------- launch ----------------
extern "C" void kernel_launch(void* const* d_in, const int* in_sizes, int n_in,
                              void* d_out, int out_size)
{
    const float* bows = (const float*)d_in[0];
    const int*   times = (const int*)d_in[1];
    const float* rnn  = (const float*)d_in[2];
    const float* rho  = (const float*)d_in[3];
    const float* mua  = (const float*)d_in[4];
    const float* lsa  = (const float*)d_in[5];
    const float* qW1  = (const float*)d_in[6];
    const float* qb1  = (const float*)d_in[7];
    const float* qW2  = (const float*)d_in[8];
    const float* qb2  = (const float*)d_in[9];
    const float* mtW  = (const float*)d_in[10];
    const float* mtb  = (const float*)d_in[11];
    const float* ltW  = (const float*)d_in[12];
    const float* ltb  = (const float*)d_in[13];
    const float* emW  = (const float*)d_in[14];
    const float* emb  = (const float*)d_in[15];
    const float* Wih  = (const float*)d_in[16];
    const float* Whh  = (const float*)d_in[17];
    const float* bih  = (const float*)d_in[18];
    const float* bhh  = (const float*)d_in[19];
    const float* meW  = (const float*)d_in[20];
    const float* meb  = (const float*)d_in[21];
    const float* leW  = (const float*)d_in[22];
    const float* leb  = (const float*)d_in[23];
    float* out = (float*)d_out;

    float *E, *Z, *X, *G0, *etas, *enc, *h1, *h2, *w, *w1p, *part;
    __nv_bfloat16 *aTh, *rhh;
    double* acc;
    cudaGetSymbolAddress((void**)&E, g_E);
    cudaGetSymbolAddress((void**)&Z, g_Z);
    cudaGetSymbolAddress((void**)&X, g_x);
    cudaGetSymbolAddress((void**)&G0, g_gates0);
    cudaGetSymbolAddress((void**)&etas, g_etas);
    cudaGetSymbolAddress((void**)&enc, g_enc);
    cudaGetSymbolAddress((void**)&h1, g_h1);
    cudaGetSymbolAddress((void**)&h2, g_h2);
    cudaGetSymbolAddress((void**)&w, g_w);
    cudaGetSymbolAddress((void**)&w1p, g_w1p);
    cudaGetSymbolAddress((void**)&part, g_part);
    cudaGetSymbolAddress((void**)&aTh, g_aTh);
    cudaGetSymbolAddress((void**)&rhh, g_rhh);
    cudaGetSymbolAddress((void**)&acc, g_acc);

    cudaFuncSetAttribute(rec_pipeline, cudaFuncAttributeMaxDynamicSharedMemorySize, REC_SMEM);

    static cudaStream_t s2 = nullptr;
    static cudaEvent_t evA = nullptr, evB = nullptr, evC = nullptr;
    if (!s2) {
        cudaStreamCreateWithFlags(&s2, cudaStreamNonBlocking);
        cudaEventCreateWithFlags(&evA, cudaEventDisableTiming);
        cudaEventCreateWithFlags(&evB, cudaEventDisableTiming);
        cudaEventCreateWithFlags(&evC, cudaEventDisableTiming);
    }

    // ---- main chain ----
    k_init<<<256, 256>>>();
    cudaEventRecord(evA, 0);

    // eta_map: X = rnn @ emW.T + emb
    gemm_nt<<<dim3(2, 1, 105), 256>>>(rnn, emW, part, T_, H_, V_, V_, V_);
    k_red<<<79, 256>>>(X, part, emb, T_, H_, 105, 0);

    // precompute layer-0 input gates: G0 = X @ Wih0.T  (bias added inside rec)
    gemm_nt<<<dim3(7, 1, 25), 256>>>(X, Wih, part, T_, 4 * H_, H_, H_, H_);
    k_red<<<313, 256>>>(G0, part, nullptr, T_, 4 * H_, 25, 0);

    // fused 3-layer LSTM + eta pipeline
    rec_pipeline<<<25, 256, REC_SMEM>>>(G0, Wih, Whh, bih, bhh, meW, meb, leW, leb, etas, acc);

    // ---- side stream: preps + beta + alpha ----
    cudaStreamWaitEvent(s2, evA, 0);
    k_prep_beta<<<2048, 256, 0, s2>>>(rho, mua);
    k_prep_w1<<<1024, 256, 0, s2>>>(qW1);
    k_enc_bows<<<B_, 256, 0, s2>>>(bows, enc);
    cudaEventRecord(evC, s2);
    beta_mma<<<dim3(NP / 128, MP / 128), 256, 0, s2>>>(aTh, rhh, E, Z);
    k_alpha<<<768, 256, 0, s2>>>(mua, lsa, acc);
    cudaEventRecord(evB, s2);

    // ---- main chain continues ----
    k_enc_eta<<<B_, 64>>>(times, etas, enc);

    cudaStreamWaitEvent(0, evC, 0);
    gemm_nt<<<dim3(7, 1, 63), 256>>>(enc, w1p, part, B_, EN_, VKP_, VKP_, VKP_);
    k_red<<<400, 256>>>(h1, part, qb1, B_, EN_, 63, 1);
    gemm_nt<<<dim3(7, 1, 15), 256>>>(h1, qW2, part, B_, EN_, EN_, EN_, EN_);
    k_red<<<400, 256>>>(h2, part, qb2, B_, EN_, 15, 1);

    cudaStreamWaitEvent(0, evB, 0);
    k_theta<<<B_, 128>>>(h2, mtW, mtb, ltW, ltb, times, etas, Z, w, acc);
    k_nll<<<dim3((V_ + 255) / 256, B_), 256>>>(bows, times, w, E, acc);
    k_final<<<1, 1>>>(out, acc);
}

// round 16
// speedup vs baseline: 1.3585x; 1.3585x over previous
#include <cuda_runtime.h>
#include <cuda_bf16.h>
#include <cstdint>
#include <math.h>

#define V_ 10000
#define T_ 100
#define K_ 50
#define R_ 300
#define H_ 200
#define EN_ 800
#define B_ 128
#define TK_ 5000
#define VKP_ 10056
#define COEFF 781.25
// beta MMA tiling
#define KP 320
#define MP 5120
#define NP 10240
typedef unsigned long long ull;

// ---------------- static device scratch (allocation-free) ----------------
__device__ __align__(16) float g_E[(size_t)TK_ * V_];     // exp(logits), 200MB
__device__ float  g_Z[TK_];                                // softmax denominators
__device__ double g_acc[4];                                // nll, kl_eta, kl_theta, kl_alpha (raw)
__device__ int    g_step[3 * T_];                          // pipeline arrival counters
__device__ __align__(16) float g_x[T_ * H_];               // eta_map output (layer0 input)
__device__ __align__(16) float g_seq3[3][T_ * H_];         // per-layer LSTM outputs
__device__ float  g_etas[T_ * K_];
__device__ __align__(16) float g_enc[(size_t)B_ * VKP_];
__device__ __align__(16) float g_h1[B_ * EN_];
__device__ __align__(16) float g_h2[B_ * EN_];
__device__ float  g_w[B_ * K_];
__device__ __align__(16) float g_w1p[(size_t)EN_ * VKP_];
__device__ __align__(16) __nv_bfloat16 g_aTh[(size_t)MP * KP];  // alphas bf16 [MP,KP]
__device__ __align__(16) __nv_bfloat16 g_rhh[(size_t)NP * KP];  // rho bf16 [NP,KP]
__device__ __align__(16) float g_part[(size_t)63 * B_ * EN_];   // split-K partial slabs (25.8MB)

#define WSTRIDE 204
#define REC_SMEM ((2 * 100 * WSTRIDE + 2 * WSTRIDE + 100 + 32) * 4)

__device__ __forceinline__ float exp_acc(float x) { return (float)exp((double)x); }
__device__ __forceinline__ float hsum2(ull a) {
    return __uint_as_float((unsigned)a) + __uint_as_float((unsigned)(a >> 32));
}
#define FMA2(acc, a, b) asm("fma.rn.f32x2 %0,%1,%2,%3;" : "=l"(acc) : "l"(a), "l"(b), "l"(acc))

// ---------------- init / prep ----------------
__global__ void k_init() {
    int i0 = blockIdx.x * blockDim.x + threadIdx.x;
    int st = gridDim.x * blockDim.x;
    for (int i = i0; i < TK_; i += st) g_Z[i] = 0.f;
    for (int i = i0; i < 3 * T_; i += st) g_step[i] = 0;
    if (i0 < 4) g_acc[i0] = 0.0;
}

// bf16 beta operands (zero-padded)
__global__ void k_prep_beta(const float* __restrict__ rho, const float* __restrict__ mua) {
    size_t i0 = (size_t)blockIdx.x * blockDim.x + threadIdx.x;
    size_t st = (size_t)gridDim.x * blockDim.x;
    for (size_t i = i0; i < (size_t)NP * KP; i += st) {
        int n = (int)(i / KP), k = (int)(i % KP);
        g_rhh[i] = (n < V_ && k < R_) ? __float2bfloat16(rho[(size_t)n * R_ + k]) : __float2bfloat16(0.f);
    }
    for (size_t i = i0; i < (size_t)MP * KP; i += st) {
        int m = (int)(i / KP), r = (int)(i % KP);
        int t = m / K_, kk = m % K_;
        g_aTh[i] = (m < TK_ && r < R_) ? __float2bfloat16(mua[((size_t)kk * T_ + t) * R_ + r])
                                       : __float2bfloat16(0.f);
    }
}

__global__ void k_prep_w1(const float* __restrict__ qW1) {
    size_t i0 = (size_t)blockIdx.x * blockDim.x + threadIdx.x;
    size_t st = (size_t)gridDim.x * blockDim.x;
    for (size_t i = i0; i < (size_t)EN_ * VKP_; i += st) {
        int e = (int)(i / VKP_), j = (int)(i % VKP_);
        g_w1p[i] = (j < V_ + K_) ? qW1[(size_t)e * (V_ + K_) + j] : 0.f;
    }
}

// ---------------- beta via mma.sync bf16 (HMMA): E = exp(A@B^T), Z row sums ----------------
__global__ __launch_bounds__(256) void beta_mma(
    const __nv_bfloat16* __restrict__ Ah, const __nv_bfloat16* __restrict__ Bh,
    float* __restrict__ E, float* __restrict__ Zr)
{
    __shared__ __align__(16) uint32_t sA[128 * 20];
    __shared__ __align__(16) uint32_t sB[128 * 20];
    __shared__ float zs[128];

    int tid = threadIdx.x;
    int lane = tid & 31, wid = tid >> 5;
    int mw = wid >> 1, nw = wid & 1;
    int gr = lane >> 2, cl = lane & 3;
    int m0 = blockIdx.y * 128, n0 = blockIdx.x * 128;

    float c[2][8][4];
#pragma unroll
    for (int mi = 0; mi < 2; mi++)
#pragma unroll
        for (int ni = 0; ni < 8; ni++)
#pragma unroll
            for (int q = 0; q < 4; q++) c[mi][ni][q] = 0.f;

    if (tid < 128) zs[tid] = 0.f;

    int lrow = tid >> 1;
    int lkk = (tid & 1) * 16;

    for (int ch = 0; ch < 10; ch++) {
        const __nv_bfloat16* Ap = Ah + (size_t)(m0 + lrow) * KP + ch * 32 + lkk;
        const __nv_bfloat16* Bp = Bh + (size_t)(n0 + lrow) * KP + ch * 32 + lkk;
        float4 av0 = *(const float4*)Ap;
        float4 av1 = *(const float4*)(Ap + 8);
        float4 bv0 = *(const float4*)Bp;
        float4 bv1 = *(const float4*)(Bp + 8);
        __syncthreads();
        *(float4*)&sA[lrow * 20 + (lkk >> 1)]     = av0;
        *(float4*)&sA[lrow * 20 + (lkk >> 1) + 4] = av1;
        *(float4*)&sB[lrow * 20 + (lkk >> 1)]     = bv0;
        *(float4*)&sB[lrow * 20 + (lkk >> 1) + 4] = bv1;
        __syncthreads();
#pragma unroll
        for (int ks = 0; ks < 2; ks++) {
            int kw = ks * 8;
            uint32_t af[2][4];
#pragma unroll
            for (int mi = 0; mi < 2; mi++) {
                int r0 = mw * 32 + mi * 16 + gr;
                af[mi][0] = sA[r0 * 20 + kw + cl];
                af[mi][1] = sA[(r0 + 8) * 20 + kw + cl];
                af[mi][2] = sA[r0 * 20 + kw + cl + 4];
                af[mi][3] = sA[(r0 + 8) * 20 + kw + cl + 4];
            }
#pragma unroll
            for (int ni = 0; ni < 8; ni++) {
                int nr = nw * 64 + ni * 8 + gr;
                uint32_t b0 = sB[nr * 20 + kw + cl];
                uint32_t b1 = sB[nr * 20 + kw + cl + 4];
#pragma unroll
                for (int mi = 0; mi < 2; mi++) {
                    asm volatile(
                        "mma.sync.aligned.m16n8k16.row.col.f32.bf16.bf16.f32 "
                        "{%0,%1,%2,%3}, {%4,%5,%6,%7}, {%8,%9}, {%0,%1,%2,%3};"
                        : "+f"(c[mi][ni][0]), "+f"(c[mi][ni][1]),
                          "+f"(c[mi][ni][2]), "+f"(c[mi][ni][3])
                        : "r"(af[mi][0]), "r"(af[mi][1]), "r"(af[mi][2]), "r"(af[mi][3]),
                          "r"(b0), "r"(b1));
                }
            }
        }
    }

#pragma unroll
    for (int mi = 0; mi < 2; mi++) {
        int lr0 = mw * 32 + mi * 16 + gr;
        int lr1 = lr0 + 8;
        int grow0 = m0 + lr0, grow1 = m0 + lr1;
        float z0 = 0.f, z1 = 0.f;
#pragma unroll
        for (int ni = 0; ni < 8; ni++) {
            int col = n0 + nw * 64 + ni * 8 + cl * 2;
            float e0 = expf(c[mi][ni][0]);
            float e1 = expf(c[mi][ni][1]);
            float e2 = expf(c[mi][ni][2]);
            float e3 = expf(c[mi][ni][3]);
            bool c0ok = col < V_, c1ok = col + 1 < V_;
            if (grow0 < TK_) {
                if (c1ok)      *(float2*)&E[(size_t)grow0 * V_ + col] = make_float2(e0, e1);
                else if (c0ok) E[(size_t)grow0 * V_ + col] = e0;
            }
            if (grow1 < TK_) {
                if (c1ok)      *(float2*)&E[(size_t)grow1 * V_ + col] = make_float2(e2, e3);
                else if (c0ok) E[(size_t)grow1 * V_ + col] = e2;
            }
            if (c0ok) { z0 += e0; z1 += e2; }
            if (c1ok) { z0 += e1; z1 += e3; }
        }
        z0 += __shfl_xor_sync(0xFFFFFFFF, z0, 1);
        z0 += __shfl_xor_sync(0xFFFFFFFF, z0, 2);
        z1 += __shfl_xor_sync(0xFFFFFFFF, z1, 1);
        z1 += __shfl_xor_sync(0xFFFFFFFF, z1, 2);
        if (cl == 0) {
            atomicAdd(&zs[lr0], z0);
            atomicAdd(&zs[lr1], z1);
        }
    }
    __syncthreads();
    if (tid < 128 && m0 + tid < TK_) atomicAdd(&Zr[m0 + tid], zs[tid]);
}

// ---------------- fused recurrent pipeline: 3 LSTM layers + eta scan ----------------
// CTAs 0..23: layer l = cta/8, slice s = cta%8 (25 gate-quads each).
// CTA 24: eta scan. Counter sync (proven R12/R14 pattern); loaders poll directly.
__global__ __launch_bounds__(256) void rec_pipeline(
    const float* __restrict__ x0,
    const float* __restrict__ Wih, const float* __restrict__ Whh,
    const float* __restrict__ bih, const float* __restrict__ bhh,
    const float* __restrict__ Wm, const float* __restrict__ bm,
    const float* __restrict__ Wl, const float* __restrict__ bl,
    float* __restrict__ etas, double* acc)
{
    extern __shared__ float smf[];
    int cta = blockIdx.x, tid = threadIdx.x;

    if (cta < 24) {
        int l = cta >> 3, s = cta & 7;
        float* Wih_s = smf;
        float* Whh_s = smf + 100 * WSTRIDE;
        float* x_s   = smf + 2 * 100 * WSTRIDE;
        float* h_s   = x_s + WSTRIDE;
        float* gb    = h_s + WSTRIDE;
        float* c_s   = gb + 100;

        for (int i = tid; i < 100 * 200; i += 256) {
            int rl = i / 200, h = i % 200;
            int grow = (rl / 25) * 200 + s * 25 + (rl % 25);
            Wih_s[rl * WSTRIDE + h] = Wih[(size_t)l * 800 * 200 + (size_t)grow * 200 + h];
            Whh_s[rl * WSTRIDE + h] = Whh[(size_t)l * 800 * 200 + (size_t)grow * 200 + h];
        }
        float bias = 0.f;
        if (tid < 100) {
            int grow = (tid / 25) * 200 + s * 25 + (tid % 25);
            bias = bih[l * 800 + grow] + bhh[l * 800 + grow];
        }
        if (tid < 25) c_s[tid] = 0.f;
        if (tid < 200) h_s[tid] = 0.f;
        __syncthreads();

        volatile int* vprev = &g_step[(l > 0 ? l - 1 : 0) * T_];
        volatile int* vown  = &g_step[l * T_];

        for (int t = 0; t < 100; t++) {
            // all loader threads poll directly, then fence+load (no tid0 bottleneck)
            if (tid < 200) {
                if (t > 0) { while (vown[t - 1] < 8) { } }
                if (l > 0) { while (vprev[t] < 8) { } }
                __threadfence();
                x_s[tid] = (l == 0) ? x0[t * 200 + tid] : __ldcg(&g_seq3[l - 1][t * 200 + tid]);
                if (t > 0) h_s[tid] = __ldcg(&g_seq3[l][(t - 1) * 200 + tid]);
            }
            __syncthreads();
            if (tid < 100) {
                const ulonglong2* wi2 = (const ulonglong2*)&Wih_s[tid * WSTRIDE];
                const ulonglong2* wh2 = (const ulonglong2*)&Whh_s[tid * WSTRIDE];
                const ulonglong2* xx  = (const ulonglong2*)x_s;
                const ulonglong2* hh  = (const ulonglong2*)h_s;
                ull a0 = 0, a1 = 0, b0 = 0, b1 = 0;
#pragma unroll 10
                for (int q = 0; q < 50; q++) {
                    ulonglong2 wi = wi2[q], wh = wh2[q], xv = xx[q], hv = hh[q];
                    FMA2(a0, wi.x, xv.x);
                    FMA2(a1, wi.y, xv.y);
                    FMA2(b0, wh.x, hv.x);
                    FMA2(b1, wh.y, hv.y);
                }
                gb[tid] = ((hsum2(a0) + hsum2(a1)) + (hsum2(b0) + hsum2(b1))) + bias;
            }
            __syncthreads();
            if (tid < 25) {
                float ig = 1.f / (1.f + expf(-gb[tid]));
                float fg = 1.f / (1.f + expf(-gb[25 + tid]));
                float gg = tanhf(gb[50 + tid]);
                float og = 1.f / (1.f + expf(-gb[75 + tid]));
                float c = fg * c_s[tid] + ig * gg;
                c_s[tid] = c;
                float hn = og * tanhf(c);
                __stcg(&g_seq3[l][t * 200 + s * 25 + tid], hn);
                __threadfence();
            }
            __syncthreads();
            if (tid == 0) atomicAdd(&g_step[l * T_ + t], 1);
        }
    } else {
        float* Wms = smf;
        float* Wls = Wms + 50 * 251;
        float* x_s = Wls + 50 * 251;
        float* mu_s = x_s + 256;
        float* ls_s = mu_s + 50;
        float* ep = ls_s + 50;
        double* dred = (double*)(ep + 50);
        for (int i = tid; i < 50 * 250; i += 256) {
            int r = i / 250, c = i % 250;
            Wms[r * 251 + c] = Wm[i];
            Wls[r * 251 + c] = Wl[i];
        }
        if (tid < 50) ep[tid] = 0.f;
        __syncthreads();
        const float LOGD = (float)log(0.005);
        const float DEN1 = 1.0f + 1e-6f;
        const float DEND = __fadd_rn(exp_acc(LOGD), 1e-6f);
        volatile int* v2 = &g_step[2 * T_];
        double kl = 0.0;
        for (int t = 0; t < 100; t++) {
            if (tid < 200) {
                while (v2[t] < 8) { }
                __threadfence();
                x_s[tid] = __ldcg(&g_seq3[2][t * 200 + tid]);
            } else if (tid < 250) {
                x_s[tid] = ep[tid - 200];   // written by tid<50 last iter; prior sync covers
            }
            __syncthreads();
            if (tid < 50) {
                const float* w = &Wms[tid * 251];
                float a0 = 0.f, a1 = 0.f;
#pragma unroll 5
                for (int h = 0; h < 250; h += 2) { a0 += w[h] * x_s[h]; a1 += w[h + 1] * x_s[h + 1]; }
                mu_s[tid] = a0 + a1 + bm[tid];
            } else if (tid >= 64 && tid < 114) {
                int k = tid - 64;
                const float* w = &Wls[k * 251];
                float a0 = 0.f, a1 = 0.f;
#pragma unroll 5
                for (int h = 0; h < 250; h += 2) { a0 += w[h] * x_s[h]; a1 += w[h + 1] * x_s[h + 1]; }
                ls_s[k] = a0 + a1 + bl[k];
            }
            __syncthreads();
            if (tid < 50) {
                float mu = mu_s[tid], ls = ls_s[tid], pmu = ep[tid];
                float pls = (t == 0) ? 0.f : LOGD;
                float den = (t == 0) ? DEN1 : DEND;
                float d  = __fadd_rn(mu, -pmu);
                float d2 = __fmul_rn(d, d);
                float Ex = exp_acc(ls);
                float S  = __fadd_rn(Ex, d2);
                float Q  = __fdiv_rn(S, den);
                float t1 = __fadd_rn(Q, -1.0f);
                float t2 = __fadd_rn(t1, pls);
                kl += (double)__fadd_rn(t2, -ls);
                etas[t * 50 + tid] = mu;
                ep[tid] = mu;
            }
            __syncthreads();
        }
        if (tid < 64) {
            for (int o = 16; o > 0; o >>= 1)
                kl += __shfl_down_sync(0xFFFFFFFF, kl, o);
            if ((tid & 31) == 0) dred[tid >> 5] = kl;
        }
        __syncthreads();
        if (tid == 0) atomicAdd(&acc[1], 0.5 * (dred[0] + dred[1]));
    }
}

// ---------------- NT SGEMM, f32x2 FFMA, split-K -> partial slabs ----------------
__global__ __launch_bounds__(256) void gemm_nt(
    const float* __restrict__ A, const float* __restrict__ B,
    float* __restrict__ P, int M, int N, int K, int lda, int ldb)
{
    __shared__ __align__(16) float As[2][8][128];
    __shared__ __align__(16) float Bs[2][8][128];
    int tid = threadIdx.x, tx = tid & 15, ty = tid >> 4;
    int row0 = blockIdx.y * 128, col0 = blockIdx.x * 128;
    int nk = K >> 3;
    int cps = (nk + gridDim.z - 1) / gridDim.z;
    int kc0 = blockIdx.z * cps, kc1 = min(nk, kc0 + cps);
    float* Pz = P + (size_t)blockIdx.z * M * N;

    if (kc0 >= kc1) {
#pragma unroll
        for (int i = 0; i < 8; i++) {
            int m = row0 + ty * 8 + i;
            if (m >= M) continue;
#pragma unroll
            for (int j = 0; j < 8; j++) {
                int n = col0 + tx * 8 + j;
                if (n < N) Pz[(size_t)m * N + n] = 0.f;
            }
        }
        return;
    }

    ull acc[8][4];
#pragma unroll
    for (int i = 0; i < 8; i++)
#pragma unroll
        for (int j = 0; j < 4; j++) acc[i][j] = 0ULL;

    int arow = tid >> 1, akq = (tid & 1) << 2;
    const float* Ap = A + (size_t)(row0 + arow) * lda + akq;
    const float* Bp = B + (size_t)(col0 + arow) * ldb + akq;
    bool am = (row0 + arow) < M, bn = (col0 + arow) < N;
    {
        int kb = kc0 << 3;
        float4 va = make_float4(0.f, 0.f, 0.f, 0.f);
        float4 vb = make_float4(0.f, 0.f, 0.f, 0.f);
        if (am) va = *(const float4*)(Ap + kb);
        if (bn) vb = *(const float4*)(Bp + kb);
        As[0][akq + 0][arow] = va.x; As[0][akq + 1][arow] = va.y;
        As[0][akq + 2][arow] = va.z; As[0][akq + 3][arow] = va.w;
        Bs[0][akq + 0][arow] = vb.x; Bs[0][akq + 1][arow] = vb.y;
        Bs[0][akq + 2][arow] = vb.z; Bs[0][akq + 3][arow] = vb.w;
    }
    __syncthreads();
    for (int kc = kc0; kc < kc1; kc++) {
        int cur = (kc - kc0) & 1;
        bool more = (kc + 1 < kc1);
        float4 va2 = make_float4(0.f, 0.f, 0.f, 0.f);
        float4 vb2 = make_float4(0.f, 0.f, 0.f, 0.f);
        if (more) {
            int kb2 = (kc + 1) << 3;
            if (am) va2 = *(const float4*)(Ap + kb2);
            if (bn) vb2 = *(const float4*)(Bp + kb2);
        }
#pragma unroll
        for (int k = 0; k < 8; k++) {
            ull a2[8], b2[4];
            const ull* brow = (const ull*)&Bs[cur][k][0];
#pragma unroll
            for (int j = 0; j < 4; j++) b2[j] = brow[tx * 4 + j];
#pragma unroll
            for (int i = 0; i < 8; i++) {
                unsigned u = __float_as_uint(As[cur][k][ty * 8 + i]);
                asm("mov.b64 %0,{%1,%1};" : "=l"(a2[i]) : "r"(u));
            }
#pragma unroll
            for (int i = 0; i < 8; i++)
#pragma unroll
                for (int j = 0; j < 4; j++)
                    asm("fma.rn.f32x2 %0,%1,%2,%3;"
                        : "=l"(acc[i][j]) : "l"(a2[i]), "l"(b2[j]), "l"(acc[i][j]));
        }
        if (more) {
            int nxt = cur ^ 1;
            As[nxt][akq + 0][arow] = va2.x; As[nxt][akq + 1][arow] = va2.y;
            As[nxt][akq + 2][arow] = va2.z; As[nxt][akq + 3][arow] = va2.w;
            Bs[nxt][akq + 0][arow] = vb2.x; Bs[nxt][akq + 1][arow] = vb2.y;
            Bs[nxt][akq + 2][arow] = vb2.z; Bs[nxt][akq + 3][arow] = vb2.w;
        }
        __syncthreads();
    }
#pragma unroll
    for (int i = 0; i < 8; i++) {
        int m = row0 + ty * 8 + i;
        if (m >= M) continue;
#pragma unroll
        for (int j = 0; j < 4; j++) {
            int n = col0 + tx * 8 + 2 * j;
            float lo = __uint_as_float((unsigned)acc[i][j]);
            float hi = __uint_as_float((unsigned)(acc[i][j] >> 32));
            if (n < N) Pz[(size_t)m * N + n] = lo;
            if (n + 1 < N) Pz[(size_t)m * N + n + 1] = hi;
        }
    }
}

// ---------------- reduce partial slabs + optional bias (+relu) ----------------
__global__ void k_red(float* __restrict__ C, const float* __restrict__ P,
                      const float* __restrict__ b1, int M, int N, int nz, int relu) {
    int tot = M * N;
    size_t slab = (size_t)M * N;
    for (int i = blockIdx.x * blockDim.x + threadIdx.x; i < tot; i += gridDim.x * blockDim.x) {
        float v = b1 ? b1[i % N] : 0.f;
        for (int z = 0; z < nz; z++) v += P[(size_t)z * slab + i];
        if (relu) v = fmaxf(v, 0.f);
        C[i] = v;
    }
}

// ---------------- encoder input build: bows part (side stream) ----------------
__global__ void k_enc_bows(const float* __restrict__ bows, float* __restrict__ enc)
{
    __shared__ float red[256];
    __shared__ float inv;
    int b = blockIdx.x, tid = threadIdx.x;
    float s = 0.f;
    for (int v = tid; v < V_; v += 256) s += bows[(size_t)b * V_ + v];
    red[tid] = s; __syncthreads();
    for (int st = 128; st > 0; st >>= 1) { if (tid < st) red[tid] += red[tid + st]; __syncthreads(); }
    if (tid == 0) inv = 1.f / red[0];
    __syncthreads();
    for (int v = tid; v < V_; v += 256) enc[(size_t)b * VKP_ + v] = bows[(size_t)b * V_ + v] * inv;
    if (tid >= 50 && tid < 56) enc[(size_t)b * VKP_ + V_ + tid] = 0.f;
}

// ---------------- encoder input: eta columns (main, after rec) ----------------
__global__ void k_enc_eta(const int* __restrict__ times, const float* __restrict__ etas,
                          float* __restrict__ enc)
{
    int b = blockIdx.x, tid = threadIdx.x;
    int t = times[b];
    if (tid < 50) enc[(size_t)b * VKP_ + V_ + tid] = etas[t * 50 + tid];
}

// ---------------- theta head ----------------
__global__ __launch_bounds__(128) void k_theta(const float* __restrict__ h2,
    const float* __restrict__ Wm, const float* __restrict__ bm,
    const float* __restrict__ Wl, const float* __restrict__ bl,
    const int* __restrict__ times, const float* __restrict__ etas,
    const float* __restrict__ Z, float* __restrict__ w, double* acc)
{
    __shared__ float hs[800], mu[50], ls[50], term[50];
    __shared__ float mx, sz;
    int b = blockIdx.x, tid = threadIdx.x;
    for (int i = tid; i < 800; i += 128) hs[i] = h2[b * 800 + i];
    __syncthreads();
    if (tid < 50) {
        const float* wr = &Wm[tid * 800];
        float a0 = 0.f, a1 = 0.f;
        for (int e = 0; e < 800; e += 2) { a0 += wr[e] * hs[e]; a1 += wr[e + 1] * hs[e + 1]; }
        mu[tid] = a0 + a1 + bm[tid];
    } else if (tid >= 64 && tid < 114) {
        int k = tid - 64;
        const float* wr = &Wl[k * 800];
        float a0 = 0.f, a1 = 0.f;
        for (int e = 0; e < 800; e += 2) { a0 += wr[e] * hs[e]; a1 += wr[e + 1] * hs[e + 1]; }
        ls[k] = a0 + a1 + bl[k];
    }
    __syncthreads();
    if (tid == 0) {
        float m = mu[0];
        for (int k = 1; k < 50; k++) m = fmaxf(m, mu[k]);
        float s = 0.f;
        for (int k = 0; k < 50; k++) s += expf(mu[k] - m);
        mx = m; sz = s;
    }
    __syncthreads();
    int t = times[b];
    if (tid < 50) {
        float th = expf(mu[tid] - mx) / sz;
        w[b * 50 + tid] = th / Z[t * 50 + tid];
        float pmu = etas[t * 50 + tid];
        float d  = __fadd_rn(mu[tid], -pmu);
        float d2 = __fmul_rn(d, d);
        float Ex = exp_acc(ls[tid]);
        float S  = __fadd_rn(Ex, d2);
        float Q  = __fdiv_rn(S, 1.0f + 1e-6f);
        float t1 = __fadd_rn(Q, -1.0f);
        term[tid] = __fadd_rn(t1, -ls[tid]);
    }
    __syncthreads();
    if (tid == 0) {
        double s = 0.0;
        for (int k = 0; k < 50; k++) s += (double)term[k];
        atomicAdd(&acc[2], 0.5 * s);
    }
}

// ---------------- NLL ----------------
__global__ __launch_bounds__(256) void k_nll(const float* __restrict__ bows,
    const int* __restrict__ times, const float* __restrict__ w,
    const float* __restrict__ E, double* acc)
{
    __shared__ float ws[50];
    __shared__ double red[256];
    int b = blockIdx.y, tid = threadIdx.x;
    int v = blockIdx.x * 256 + tid;
    if (tid < 50) ws[tid] = w[b * 50 + tid];
    __syncthreads();
    double local = 0.0;
    if (v < V_) {
        const float* Eb = E + (size_t)(times[b] * 50) * V_ + v;
        float a = 0.f;
#pragma unroll 10
        for (int k = 0; k < 50; k++) a += ws[k] * Eb[(size_t)k * V_];
        local = -(double)logf(a + 1e-12f) * (double)bows[(size_t)b * V_ + v];
    }
    red[tid] = local; __syncthreads();
    for (int st = 128; st > 0; st >>= 1) { if (tid < st) red[tid] += red[tid + st]; __syncthreads(); }
    if (tid == 0) atomicAdd(&acc[0], red[0]);
}

// ---------------- alpha KL ----------------
__global__ __launch_bounds__(256) void k_alpha(const float* __restrict__ mua,
                                               const float* __restrict__ lsa, double* acc)
{
    __shared__ double red[256];
    const float LOGD = (float)log(0.005);
    const float DEN1 = 1.0f + 1e-6f;
    const float DEND = __fadd_rn(exp_acc(LOGD), 1e-6f);
    int tid = threadIdx.x;
    double local = 0.0;
    int tot = K_ * T_ * R_;
    for (int idx = blockIdx.x * 256 + tid; idx < tot; idx += gridDim.x * 256) {
        int t = (idx / R_) % T_;
        float mu = mua[idx], ls = lsa[idx];
        float pmu = (t == 0) ? 0.f : mua[idx - R_];
        float pls = (t == 0) ? 0.f : LOGD;
        float den = (t == 0) ? DEN1 : DEND;
        float d  = __fadd_rn(mu, -pmu);
        float d2 = __fmul_rn(d, d);
        float Ex = expf(ls);
        float S  = __fadd_rn(Ex, d2);
        float Q  = __fdiv_rn(S, den);
        float t1 = __fadd_rn(Q, -1.0f);
        float t2 = __fadd_rn(t1, pls);
        local += (double)__fadd_rn(t2, -ls);
    }
    red[tid] = local; __syncthreads();
    for (int st = 128; st > 0; st >>= 1) { if (tid < st) red[tid] += red[tid + st]; __syncthreads(); }
    if (tid == 0) atomicAdd(&acc[3], 0.5 * red[0]);
}

// ---------------- finalize ----------------
__global__ void k_final(float* out, const double* acc) {
    if (threadIdx.x == 0 && blockIdx.x == 0) {
        double nll = acc[0] * COEFF;
        double kle = acc[1];
        double klt = acc[2] * COEFF;
        double kla = acc[3];
        out[0] = (float)(nll + kle + klt + kla);
        out[1] = (float)nll;
        out[2] = (float)kle;
        out[3] = (float)klt;
        out[4] = (float)kla;
    }
}

// ---------------- launch ----------------
extern "C" void kernel_launch(void* const* d_in, const int* in_sizes, int n_in,
                              void* d_out, int out_size)
{
    const float* bows = (const float*)d_in[0];
    const int*   times = (const int*)d_in[1];
    const float* rnn  = (const float*)d_in[2];
    const float* rho  = (const float*)d_in[3];
    const float* mua  = (const float*)d_in[4];
    const float* lsa  = (const float*)d_in[5];
    const float* qW1  = (const float*)d_in[6];
    const float* qb1  = (const float*)d_in[7];
    const float* qW2  = (const float*)d_in[8];
    const float* qb2  = (const float*)d_in[9];
    const float* mtW  = (const float*)d_in[10];
    const float* mtb  = (const float*)d_in[11];
    const float* ltW  = (const float*)d_in[12];
    const float* ltb  = (const float*)d_in[13];
    const float* emW  = (const float*)d_in[14];
    const float* emb  = (const float*)d_in[15];
    const float* Wih  = (const float*)d_in[16];
    const float* Whh  = (const float*)d_in[17];
    const float* bih  = (const float*)d_in[18];
    const float* bhh  = (const float*)d_in[19];
    const float* meW  = (const float*)d_in[20];
    const float* meb  = (const float*)d_in[21];
    const float* leW  = (const float*)d_in[22];
    const float* leb  = (const float*)d_in[23];
    float* out = (float*)d_out;

    float *E, *Z, *X, *etas, *enc, *h1, *h2, *w, *w1p, *part;
    __nv_bfloat16 *aTh, *rhh;
    double* acc;
    cudaGetSymbolAddress((void**)&E, g_E);
    cudaGetSymbolAddress((void**)&Z, g_Z);
    cudaGetSymbolAddress((void**)&X, g_x);
    cudaGetSymbolAddress((void**)&etas, g_etas);
    cudaGetSymbolAddress((void**)&enc, g_enc);
    cudaGetSymbolAddress((void**)&h1, g_h1);
    cudaGetSymbolAddress((void**)&h2, g_h2);
    cudaGetSymbolAddress((void**)&w, g_w);
    cudaGetSymbolAddress((void**)&w1p, g_w1p);
    cudaGetSymbolAddress((void**)&part, g_part);
    cudaGetSymbolAddress((void**)&aTh, g_aTh);
    cudaGetSymbolAddress((void**)&rhh, g_rhh);
    cudaGetSymbolAddress((void**)&acc, g_acc);

    cudaFuncSetAttribute(rec_pipeline, cudaFuncAttributeMaxDynamicSharedMemorySize, REC_SMEM);

    static cudaStream_t s2 = nullptr;
    static cudaEvent_t evA = nullptr, evB = nullptr, evC = nullptr;
    if (!s2) {
        cudaStreamCreateWithFlags(&s2, cudaStreamNonBlocking);
        cudaEventCreateWithFlags(&evA, cudaEventDisableTiming);
        cudaEventCreateWithFlags(&evB, cudaEventDisableTiming);
        cudaEventCreateWithFlags(&evC, cudaEventDisableTiming);
    }

    // ---- main chain ----
    k_init<<<256, 256>>>();
    cudaEventRecord(evA, 0);

    // eta_map: X = rnn @ emW.T + emb
    gemm_nt<<<dim3(2, 1, 105), 256>>>(rnn, emW, part, T_, H_, V_, V_, V_);
    k_red<<<79, 256>>>(X, part, emb, T_, H_, 105, 0);

    // fused 3-layer LSTM + eta pipeline  (launch #4 -> profiled)
    rec_pipeline<<<25, 256, REC_SMEM>>>(X, Wih, Whh, bih, bhh, meW, meb, leW, leb, etas, acc);

    // ---- side stream: preps + beta + alpha ----
    cudaStreamWaitEvent(s2, evA, 0);
    k_prep_beta<<<2048, 256, 0, s2>>>(rho, mua);
    k_prep_w1<<<1024, 256, 0, s2>>>(qW1);
    k_enc_bows<<<B_, 256, 0, s2>>>(bows, enc);
    cudaEventRecord(evC, s2);
    beta_mma<<<dim3(NP / 128, MP / 128), 256, 0, s2>>>(aTh, rhh, E, Z);
    k_alpha<<<768, 256, 0, s2>>>(mua, lsa, acc);
    cudaEventRecord(evB, s2);

    // ---- main chain continues ----
    k_enc_eta<<<B_, 64>>>(times, etas, enc);

    cudaStreamWaitEvent(0, evC, 0);
    gemm_nt<<<dim3(7, 1, 63), 256>>>(enc, w1p, part, B_, EN_, VKP_, VKP_, VKP_);
    k_red<<<400, 256>>>(h1, part, qb1, B_, EN_, 63, 1);
    gemm_nt<<<dim3(7, 1, 15), 256>>>(h1, qW2, part, B_, EN_, EN_, EN_, EN_);
    k_red<<<400, 256>>>(h2, part, qb2, B_, EN_, 15, 1);

    cudaStreamWaitEvent(0, evB, 0);
    k_theta<<<B_, 128>>>(h2, mtW, mtb, ltW, ltb, times, etas, Z, w, acc);
    k_nll<<<dim3((V_ + 255) / 256, B_), 256>>>(bows, times, w, E, acc);
    k_final<<<1, 1>>>(out, acc);
}

// round 17
// speedup vs baseline: 1.6858x; 1.2410x over previous
#include <cuda_runtime.h>
#include <cuda_bf16.h>
#include <cstdint>
#include <math.h>

#define V_ 10000
#define T_ 100
#define K_ 50
#define R_ 300
#define H_ 200
#define EN_ 800
#define B_ 128
#define TK_ 5000
#define VKP_ 10056
#define COEFF 781.25
// beta MMA tiling
#define KP 320
#define MP 5120
#define NP 10240
#define G1SLAB ((size_t)B_ * EN_)          // 102400 floats per GEMM1 slab
#define ETA_OFF ((size_t)64 * G1SLAB)      // eta_map slab region starts here
typedef unsigned long long ull;

// ---------------- static device scratch (allocation-free) ----------------
__device__ __align__(16) float g_E[(size_t)TK_ * V_];     // exp(logits), 200MB
__device__ float  g_Z[TK_];                                // softmax denominators
__device__ double g_acc[4];                                // nll, kl_eta, kl_theta, kl_alpha (raw)
__device__ int    g_step[3 * T_];                          // pipeline arrival counters
__device__ __align__(16) float g_x[T_ * H_];               // eta_map output (layer0 input)
__device__ __align__(16) float g_seq3[3][T_ * H_];         // per-layer LSTM outputs
__device__ float  g_etas[T_ * K_];
__device__ __align__(16) float g_enc[(size_t)B_ * VKP_];
__device__ __align__(16) float g_h1[B_ * EN_];
__device__ __align__(16) float g_h2[B_ * EN_];
__device__ float  g_w[B_ * K_];
__device__ __align__(16) float g_w1p[(size_t)EN_ * VKP_];
__device__ __align__(16) __nv_bfloat16 g_aTh[(size_t)MP * KP];  // alphas bf16 [MP,KP]
__device__ __align__(16) __nv_bfloat16 g_rhh[(size_t)NP * KP];  // rho bf16 [NP,KP]
__device__ __align__(16) float g_part[ETA_OFF + (size_t)105 * T_ * H_];  // 64 G1 slabs + eta region

#define WSTRIDE 204
#define REC_SMEM ((2 * 100 * WSTRIDE + 2 * WSTRIDE + 100 + 32) * 4)

__device__ __forceinline__ float exp_acc(float x) { return (float)exp((double)x); }
__device__ __forceinline__ float hsum2(ull a) {
    return __uint_as_float((unsigned)a) + __uint_as_float((unsigned)(a >> 32));
}
#define FMA2(acc, a, b) asm("fma.rn.f32x2 %0,%1,%2,%3;" : "=l"(acc) : "l"(a), "l"(b), "l"(acc))

// acquire-poll until counter >= target (fence folded into load)
__device__ __forceinline__ void wait_ge(const int* p, int target) {
    int v;
    do {
        asm volatile("ld.acquire.gpu.global.s32 %0, [%1];" : "=r"(v) : "l"(p) : "memory");
    } while (v < target);
}
// release increment (orders prior CTA writes via the preceding bar)
__device__ __forceinline__ void rel_inc(int* p) {
    asm volatile("red.release.gpu.global.add.s32 [%0], 1;" :: "l"(p) : "memory");
}

// ---------------- init / prep ----------------
__global__ void k_init() {
    int i0 = blockIdx.x * blockDim.x + threadIdx.x;
    int st = gridDim.x * blockDim.x;
    for (int i = i0; i < TK_; i += st) g_Z[i] = 0.f;
    for (int i = i0; i < 3 * T_; i += st) g_step[i] = 0;
    if (i0 < 4) g_acc[i0] = 0.0;
}

__global__ void k_prep_beta(const float* __restrict__ rho, const float* __restrict__ mua) {
    size_t i0 = (size_t)blockIdx.x * blockDim.x + threadIdx.x;
    size_t st = (size_t)gridDim.x * blockDim.x;
    for (size_t i = i0; i < (size_t)NP * KP; i += st) {
        int n = (int)(i / KP), k = (int)(i % KP);
        g_rhh[i] = (n < V_ && k < R_) ? __float2bfloat16(rho[(size_t)n * R_ + k]) : __float2bfloat16(0.f);
    }
    for (size_t i = i0; i < (size_t)MP * KP; i += st) {
        int m = (int)(i / KP), r = (int)(i % KP);
        int t = m / K_, kk = m % K_;
        g_aTh[i] = (m < TK_ && r < R_) ? __float2bfloat16(mua[((size_t)kk * T_ + t) * R_ + r])
                                       : __float2bfloat16(0.f);
    }
}

__global__ void k_prep_w1(const float* __restrict__ qW1) {
    size_t i0 = (size_t)blockIdx.x * blockDim.x + threadIdx.x;
    size_t st = (size_t)gridDim.x * blockDim.x;
    for (size_t i = i0; i < (size_t)EN_ * VKP_; i += st) {
        int e = (int)(i / VKP_), j = (int)(i % VKP_);
        g_w1p[i] = (j < V_ + K_) ? qW1[(size_t)e * (V_ + K_) + j] : 0.f;
    }
}

// ---------------- beta via mma.sync bf16 (HMMA): E = exp(A@B^T), Z row sums ----------------
__global__ __launch_bounds__(256) void beta_mma(
    const __nv_bfloat16* __restrict__ Ah, const __nv_bfloat16* __restrict__ Bh,
    float* __restrict__ E, float* __restrict__ Zr)
{
    __shared__ __align__(16) uint32_t sA[128 * 20];
    __shared__ __align__(16) uint32_t sB[128 * 20];
    __shared__ float zs[128];

    int tid = threadIdx.x;
    int lane = tid & 31, wid = tid >> 5;
    int mw = wid >> 1, nw = wid & 1;
    int gr = lane >> 2, cl = lane & 3;
    int m0 = blockIdx.y * 128, n0 = blockIdx.x * 128;

    float c[2][8][4];
#pragma unroll
    for (int mi = 0; mi < 2; mi++)
#pragma unroll
        for (int ni = 0; ni < 8; ni++)
#pragma unroll
            for (int q = 0; q < 4; q++) c[mi][ni][q] = 0.f;

    if (tid < 128) zs[tid] = 0.f;

    int lrow = tid >> 1;
    int lkk = (tid & 1) * 16;

    for (int ch = 0; ch < 10; ch++) {
        const __nv_bfloat16* Ap = Ah + (size_t)(m0 + lrow) * KP + ch * 32 + lkk;
        const __nv_bfloat16* Bp = Bh + (size_t)(n0 + lrow) * KP + ch * 32 + lkk;
        float4 av0 = *(const float4*)Ap;
        float4 av1 = *(const float4*)(Ap + 8);
        float4 bv0 = *(const float4*)Bp;
        float4 bv1 = *(const float4*)(Bp + 8);
        __syncthreads();
        *(float4*)&sA[lrow * 20 + (lkk >> 1)]     = av0;
        *(float4*)&sA[lrow * 20 + (lkk >> 1) + 4] = av1;
        *(float4*)&sB[lrow * 20 + (lkk >> 1)]     = bv0;
        *(float4*)&sB[lrow * 20 + (lkk >> 1) + 4] = bv1;
        __syncthreads();
#pragma unroll
        for (int ks = 0; ks < 2; ks++) {
            int kw = ks * 8;
            uint32_t af[2][4];
#pragma unroll
            for (int mi = 0; mi < 2; mi++) {
                int r0 = mw * 32 + mi * 16 + gr;
                af[mi][0] = sA[r0 * 20 + kw + cl];
                af[mi][1] = sA[(r0 + 8) * 20 + kw + cl];
                af[mi][2] = sA[r0 * 20 + kw + cl + 4];
                af[mi][3] = sA[(r0 + 8) * 20 + kw + cl + 4];
            }
#pragma unroll
            for (int ni = 0; ni < 8; ni++) {
                int nr = nw * 64 + ni * 8 + gr;
                uint32_t b0 = sB[nr * 20 + kw + cl];
                uint32_t b1 = sB[nr * 20 + kw + cl + 4];
#pragma unroll
                for (int mi = 0; mi < 2; mi++) {
                    asm volatile(
                        "mma.sync.aligned.m16n8k16.row.col.f32.bf16.bf16.f32 "
                        "{%0,%1,%2,%3}, {%4,%5,%6,%7}, {%8,%9}, {%0,%1,%2,%3};"
                        : "+f"(c[mi][ni][0]), "+f"(c[mi][ni][1]),
                          "+f"(c[mi][ni][2]), "+f"(c[mi][ni][3])
                        : "r"(af[mi][0]), "r"(af[mi][1]), "r"(af[mi][2]), "r"(af[mi][3]),
                          "r"(b0), "r"(b1));
                }
            }
        }
    }

#pragma unroll
    for (int mi = 0; mi < 2; mi++) {
        int lr0 = mw * 32 + mi * 16 + gr;
        int lr1 = lr0 + 8;
        int grow0 = m0 + lr0, grow1 = m0 + lr1;
        float z0 = 0.f, z1 = 0.f;
#pragma unroll
        for (int ni = 0; ni < 8; ni++) {
            int col = n0 + nw * 64 + ni * 8 + cl * 2;
            float e0 = expf(c[mi][ni][0]);
            float e1 = expf(c[mi][ni][1]);
            float e2 = expf(c[mi][ni][2]);
            float e3 = expf(c[mi][ni][3]);
            bool c0ok = col < V_, c1ok = col + 1 < V_;
            if (grow0 < TK_) {
                if (c1ok)      *(float2*)&E[(size_t)grow0 * V_ + col] = make_float2(e0, e1);
                else if (c0ok) E[(size_t)grow0 * V_ + col] = e0;
            }
            if (grow1 < TK_) {
                if (c1ok)      *(float2*)&E[(size_t)grow1 * V_ + col] = make_float2(e2, e3);
                else if (c0ok) E[(size_t)grow1 * V_ + col] = e2;
            }
            if (c0ok) { z0 += e0; z1 += e2; }
            if (c1ok) { z0 += e1; z1 += e3; }
        }
        z0 += __shfl_xor_sync(0xFFFFFFFF, z0, 1);
        z0 += __shfl_xor_sync(0xFFFFFFFF, z0, 2);
        z1 += __shfl_xor_sync(0xFFFFFFFF, z1, 1);
        z1 += __shfl_xor_sync(0xFFFFFFFF, z1, 2);
        if (cl == 0) {
            atomicAdd(&zs[lr0], z0);
            atomicAdd(&zs[lr1], z1);
        }
    }
    __syncthreads();
    if (tid < 128 && m0 + tid < TK_) atomicAdd(&Zr[m0 + tid], zs[tid]);
}

// ---------------- fused recurrent pipeline: 3 LSTM layers + eta scan ----------------
// Acquire/release counter sync (no per-slot threadfence).
__global__ __launch_bounds__(256) void rec_pipeline(
    const float* __restrict__ x0,
    const float* __restrict__ Wih, const float* __restrict__ Whh,
    const float* __restrict__ bih, const float* __restrict__ bhh,
    const float* __restrict__ Wm, const float* __restrict__ bm,
    const float* __restrict__ Wl, const float* __restrict__ bl,
    float* __restrict__ etas, double* acc)
{
    extern __shared__ float smf[];
    int cta = blockIdx.x, tid = threadIdx.x;

    if (cta < 24) {
        int l = cta >> 3, s = cta & 7;
        float* Wih_s = smf;
        float* Whh_s = smf + 100 * WSTRIDE;
        float* x_s   = smf + 2 * 100 * WSTRIDE;
        float* h_s   = x_s + WSTRIDE;
        float* gb    = h_s + WSTRIDE;
        float* c_s   = gb + 100;

        for (int i = tid; i < 100 * 200; i += 256) {
            int rl = i / 200, h = i % 200;
            int grow = (rl / 25) * 200 + s * 25 + (rl % 25);
            Wih_s[rl * WSTRIDE + h] = Wih[(size_t)l * 800 * 200 + (size_t)grow * 200 + h];
            Whh_s[rl * WSTRIDE + h] = Whh[(size_t)l * 800 * 200 + (size_t)grow * 200 + h];
        }
        float bias = 0.f;
        if (tid < 100) {
            int grow = (tid / 25) * 200 + s * 25 + (tid % 25);
            bias = bih[l * 800 + grow] + bhh[l * 800 + grow];
        }
        if (tid < 25) c_s[tid] = 0.f;
        if (tid < 200) h_s[tid] = 0.f;
        __syncthreads();

        int* ctr_prev = &g_step[(l > 0 ? l - 1 : 0) * T_];
        int* ctr_own  = &g_step[l * T_];

        for (int t = 0; t < 100; t++) {
            if (tid < 200) {
                float xr = 0.f;
                if (l == 0) xr = x0[t * 200 + tid];      // prefetch before wait
                if (t > 0) wait_ge(ctr_own + (t - 1), 8);
                if (l > 0) {
                    wait_ge(ctr_prev + t, 8);
                    xr = __ldcg(&g_seq3[l - 1][t * 200 + tid]);
                }
                x_s[tid] = xr;
                if (t > 0) h_s[tid] = __ldcg(&g_seq3[l][(t - 1) * 200 + tid]);
            }
            __syncthreads();
            if (tid < 100) {
                const ulonglong2* wi2 = (const ulonglong2*)&Wih_s[tid * WSTRIDE];
                const ulonglong2* wh2 = (const ulonglong2*)&Whh_s[tid * WSTRIDE];
                const ulonglong2* xx  = (const ulonglong2*)x_s;
                const ulonglong2* hh  = (const ulonglong2*)h_s;
                ull a0 = 0, a1 = 0, b0 = 0, b1 = 0;
#pragma unroll 10
                for (int q = 0; q < 50; q++) {
                    ulonglong2 wi = wi2[q], wh = wh2[q], xv = xx[q], hv = hh[q];
                    FMA2(a0, wi.x, xv.x);
                    FMA2(a1, wi.y, xv.y);
                    FMA2(b0, wh.x, hv.x);
                    FMA2(b1, wh.y, hv.y);
                }
                gb[tid] = ((hsum2(a0) + hsum2(a1)) + (hsum2(b0) + hsum2(b1))) + bias;
            }
            __syncthreads();
            if (tid < 25) {
                float ig = 1.f / (1.f + expf(-gb[tid]));
                float fg = 1.f / (1.f + expf(-gb[25 + tid]));
                float gg = tanhf(gb[50 + tid]);
                float og = 1.f / (1.f + expf(-gb[75 + tid]));
                float c = fg * c_s[tid] + ig * gg;
                c_s[tid] = c;
                float hn = og * tanhf(c);
                __stcg(&g_seq3[l][t * 200 + s * 25 + tid], hn);
            }
            __syncthreads();                   // orders h-stores into tid0's release
            if (tid == 0) rel_inc(ctr_own + t);
        }
    } else {
        float* Wms = smf;
        float* Wls = Wms + 50 * 251;
        float* x_s = Wls + 50 * 251;
        float* mu_s = x_s + 256;
        float* ls_s = mu_s + 50;
        float* ep = ls_s + 50;
        double* dred = (double*)(ep + 50);
        for (int i = tid; i < 50 * 250; i += 256) {
            int r = i / 250, c = i % 250;
            Wms[r * 251 + c] = Wm[i];
            Wls[r * 251 + c] = Wl[i];
        }
        if (tid < 50) ep[tid] = 0.f;
        __syncthreads();
        const float LOGD = (float)log(0.005);
        const float DEN1 = 1.0f + 1e-6f;
        const float DEND = __fadd_rn(exp_acc(LOGD), 1e-6f);
        int* ctr2 = &g_step[2 * T_];
        double kl = 0.0;
        for (int t = 0; t < 100; t++) {
            if (tid < 200) {
                wait_ge(ctr2 + t, 8);
                x_s[tid] = __ldcg(&g_seq3[2][t * 200 + tid]);
            } else if (tid < 250) {
                x_s[tid] = ep[tid - 200];
            }
            __syncthreads();
            if (tid < 50) {
                const float* w = &Wms[tid * 251];
                float a0 = 0.f, a1 = 0.f;
#pragma unroll 5
                for (int h = 0; h < 250; h += 2) { a0 += w[h] * x_s[h]; a1 += w[h + 1] * x_s[h + 1]; }
                mu_s[tid] = a0 + a1 + bm[tid];
            } else if (tid >= 64 && tid < 114) {
                int k = tid - 64;
                const float* w = &Wls[k * 251];
                float a0 = 0.f, a1 = 0.f;
#pragma unroll 5
                for (int h = 0; h < 250; h += 2) { a0 += w[h] * x_s[h]; a1 += w[h + 1] * x_s[h + 1]; }
                ls_s[k] = a0 + a1 + bl[k];
            }
            __syncthreads();
            if (tid < 50) {
                float mu = mu_s[tid], ls = ls_s[tid], pmu = ep[tid];
                float pls = (t == 0) ? 0.f : LOGD;
                float den = (t == 0) ? DEN1 : DEND;
                float d  = __fadd_rn(mu, -pmu);
                float d2 = __fmul_rn(d, d);
                float Ex = exp_acc(ls);
                float S  = __fadd_rn(Ex, d2);
                float Q  = __fdiv_rn(S, den);
                float t1 = __fadd_rn(Q, -1.0f);
                float t2 = __fadd_rn(t1, pls);
                kl += (double)__fadd_rn(t2, -ls);
                etas[t * 50 + tid] = mu;
                ep[tid] = mu;
            }
            __syncthreads();
        }
        if (tid < 64) {
            for (int o = 16; o > 0; o >>= 1)
                kl += __shfl_down_sync(0xFFFFFFFF, kl, o);
            if ((tid & 31) == 0) dred[tid >> 5] = kl;
        }
        __syncthreads();
        if (tid == 0) atomicAdd(&acc[1], 0.5 * (dred[0] + dred[1]));
    }
}

// ---------------- NT SGEMM, f32x2 FFMA, split-K -> partial slabs ----------------
__global__ __launch_bounds__(256) void gemm_nt(
    const float* __restrict__ A, const float* __restrict__ B,
    float* __restrict__ P, int M, int N, int K, int lda, int ldb)
{
    __shared__ __align__(16) float As[2][8][128];
    __shared__ __align__(16) float Bs[2][8][128];
    int tid = threadIdx.x, tx = tid & 15, ty = tid >> 4;
    int row0 = blockIdx.y * 128, col0 = blockIdx.x * 128;
    int nk = K >> 3;
    int cps = (nk + gridDim.z - 1) / gridDim.z;
    int kc0 = blockIdx.z * cps, kc1 = min(nk, kc0 + cps);
    float* Pz = P + (size_t)blockIdx.z * M * N;

    if (kc0 >= kc1) {
#pragma unroll
        for (int i = 0; i < 8; i++) {
            int m = row0 + ty * 8 + i;
            if (m >= M) continue;
#pragma unroll
            for (int j = 0; j < 8; j++) {
                int n = col0 + tx * 8 + j;
                if (n < N) Pz[(size_t)m * N + n] = 0.f;
            }
        }
        return;
    }

    ull acc[8][4];
#pragma unroll
    for (int i = 0; i < 8; i++)
#pragma unroll
        for (int j = 0; j < 4; j++) acc[i][j] = 0ULL;

    int arow = tid >> 1, akq = (tid & 1) << 2;
    const float* Ap = A + (size_t)(row0 + arow) * lda + akq;
    const float* Bp = B + (size_t)(col0 + arow) * ldb + akq;
    bool am = (row0 + arow) < M, bn = (col0 + arow) < N;
    {
        int kb = kc0 << 3;
        float4 va = make_float4(0.f, 0.f, 0.f, 0.f);
        float4 vb = make_float4(0.f, 0.f, 0.f, 0.f);
        if (am) va = *(const float4*)(Ap + kb);
        if (bn) vb = *(const float4*)(Bp + kb);
        As[0][akq + 0][arow] = va.x; As[0][akq + 1][arow] = va.y;
        As[0][akq + 2][arow] = va.z; As[0][akq + 3][arow] = va.w;
        Bs[0][akq + 0][arow] = vb.x; Bs[0][akq + 1][arow] = vb.y;
        Bs[0][akq + 2][arow] = vb.z; Bs[0][akq + 3][arow] = vb.w;
    }
    __syncthreads();
    for (int kc = kc0; kc < kc1; kc++) {
        int cur = (kc - kc0) & 1;
        bool more = (kc + 1 < kc1);
        float4 va2 = make_float4(0.f, 0.f, 0.f, 0.f);
        float4 vb2 = make_float4(0.f, 0.f, 0.f, 0.f);
        if (more) {
            int kb2 = (kc + 1) << 3;
            if (am) va2 = *(const float4*)(Ap + kb2);
            if (bn) vb2 = *(const float4*)(Bp + kb2);
        }
#pragma unroll
        for (int k = 0; k < 8; k++) {
            ull a2[8], b2[4];
            const ull* brow = (const ull*)&Bs[cur][k][0];
#pragma unroll
            for (int j = 0; j < 4; j++) b2[j] = brow[tx * 4 + j];
#pragma unroll
            for (int i = 0; i < 8; i++) {
                unsigned u = __float_as_uint(As[cur][k][ty * 8 + i]);
                asm("mov.b64 %0,{%1,%1};" : "=l"(a2[i]) : "r"(u));
            }
#pragma unroll
            for (int i = 0; i < 8; i++)
#pragma unroll
                for (int j = 0; j < 4; j++)
                    asm("fma.rn.f32x2 %0,%1,%2,%3;"
                        : "=l"(acc[i][j]) : "l"(a2[i]), "l"(b2[j]), "l"(acc[i][j]));
        }
        if (more) {
            int nxt = cur ^ 1;
            As[nxt][akq + 0][arow] = va2.x; As[nxt][akq + 1][arow] = va2.y;
            As[nxt][akq + 2][arow] = va2.z; As[nxt][akq + 3][arow] = va2.w;
            Bs[nxt][akq + 0][arow] = vb2.x; Bs[nxt][akq + 1][arow] = vb2.y;
            Bs[nxt][akq + 2][arow] = vb2.z; Bs[nxt][akq + 3][arow] = vb2.w;
        }
        __syncthreads();
    }
#pragma unroll
    for (int i = 0; i < 8; i++) {
        int m = row0 + ty * 8 + i;
        if (m >= M) continue;
#pragma unroll
        for (int j = 0; j < 4; j++) {
            int n = col0 + tx * 8 + 2 * j;
            float lo = __uint_as_float((unsigned)acc[i][j]);
            float hi = __uint_as_float((unsigned)(acc[i][j] >> 32));
            if (n < N) Pz[(size_t)m * N + n] = lo;
            if (n + 1 < N) Pz[(size_t)m * N + n + 1] = hi;
        }
    }
}

// ---------------- reduce partial slabs + optional bias (+relu) ----------------
__global__ void k_red(float* __restrict__ C, const float* __restrict__ P,
                      const float* __restrict__ b1, int M, int N, int nz, int relu) {
    int tot = M * N;
    size_t slab = (size_t)M * N;
    for (int i = blockIdx.x * blockDim.x + threadIdx.x; i < tot; i += gridDim.x * blockDim.x) {
        float v = b1 ? b1[i % N] : 0.f;
        for (int z = 0; z < nz; z++) v += P[(size_t)z * slab + i];
        if (relu) v = fmaxf(v, 0.f);
        C[i] = v;
    }
}

// ---------------- encoder input build: bows part (side stream) ----------------
__global__ void k_enc_bows(const float* __restrict__ bows, float* __restrict__ enc)
{
    __shared__ float red[256];
    __shared__ float inv;
    int b = blockIdx.x, tid = threadIdx.x;
    float s = 0.f;
    for (int v = tid; v < V_; v += 256) s += bows[(size_t)b * V_ + v];
    red[tid] = s; __syncthreads();
    for (int st = 128; st > 0; st >>= 1) { if (tid < st) red[tid] += red[tid + st]; __syncthreads(); }
    if (tid == 0) inv = 1.f / red[0];
    __syncthreads();
    for (int v = tid; v < V_; v += 256) enc[(size_t)b * VKP_ + v] = bows[(size_t)b * V_ + v] * inv;
    if (tid >= 50 && tid < 56) enc[(size_t)b * VKP_ + V_ + tid] = 0.f;
}

// ---------------- encoder input: eta columns (main, after rec) ----------------
__global__ void k_enc_eta(const int* __restrict__ times, const float* __restrict__ etas,
                          float* __restrict__ enc)
{
    int b = blockIdx.x, tid = threadIdx.x;
    int t = times[b];
    if (tid < 50) enc[(size_t)b * VKP_ + V_ + tid] = etas[t * 50 + tid];
}

// ---------------- theta head ----------------
__global__ __launch_bounds__(128) void k_theta(const float* __restrict__ h2,
    const float* __restrict__ Wm, const float* __restrict__ bm,
    const float* __restrict__ Wl, const float* __restrict__ bl,
    const int* __restrict__ times, const float* __restrict__ etas,
    const float* __restrict__ Z, float* __restrict__ w, double* acc)
{
    __shared__ float hs[800], mu[50], ls[50], term[50];
    __shared__ float mx, sz;
    int b = blockIdx.x, tid = threadIdx.x;
    for (int i = tid; i < 800; i += 128) hs[i] = h2[b * 800 + i];
    __syncthreads();
    if (tid < 50) {
        const float* wr = &Wm[tid * 800];
        float a0 = 0.f, a1 = 0.f;
        for (int e = 0; e < 800; e += 2) { a0 += wr[e] * hs[e]; a1 += wr[e + 1] * hs[e + 1]; }
        mu[tid] = a0 + a1 + bm[tid];
    } else if (tid >= 64 && tid < 114) {
        int k = tid - 64;
        const float* wr = &Wl[k * 800];
        float a0 = 0.f, a1 = 0.f;
        for (int e = 0; e < 800; e += 2) { a0 += wr[e] * hs[e]; a1 += wr[e + 1] * hs[e + 1]; }
        ls[k] = a0 + a1 + bl[k];
    }
    __syncthreads();
    if (tid == 0) {
        float m = mu[0];
        for (int k = 1; k < 50; k++) m = fmaxf(m, mu[k]);
        float s = 0.f;
        for (int k = 0; k < 50; k++) s += expf(mu[k] - m);
        mx = m; sz = s;
    }
    __syncthreads();
    int t = times[b];
    if (tid < 50) {
        float th = expf(mu[tid] - mx) / sz;
        w[b * 50 + tid] = th / Z[t * 50 + tid];
        float pmu = etas[t * 50 + tid];
        float d  = __fadd_rn(mu[tid], -pmu);
        float d2 = __fmul_rn(d, d);
        float Ex = exp_acc(ls[tid]);
        float S  = __fadd_rn(Ex, d2);
        float Q  = __fdiv_rn(S, 1.0f + 1e-6f);
        float t1 = __fadd_rn(Q, -1.0f);
        term[tid] = __fadd_rn(t1, -ls[tid]);
    }
    __syncthreads();
    if (tid == 0) {
        double s = 0.0;
        for (int k = 0; k < 50; k++) s += (double)term[k];
        atomicAdd(&acc[2], 0.5 * s);
    }
}

// ---------------- NLL ----------------
__global__ __launch_bounds__(256) void k_nll(const float* __restrict__ bows,
    const int* __restrict__ times, const float* __restrict__ w,
    const float* __restrict__ E, double* acc)
{
    __shared__ float ws[50];
    __shared__ double red[256];
    int b = blockIdx.y, tid = threadIdx.x;
    int v = blockIdx.x * 256 + tid;
    if (tid < 50) ws[tid] = w[b * 50 + tid];
    __syncthreads();
    double local = 0.0;
    if (v < V_) {
        const float* Eb = E + (size_t)(times[b] * 50) * V_ + v;
        float a = 0.f;
#pragma unroll 10
        for (int k = 0; k < 50; k++) a += ws[k] * Eb[(size_t)k * V_];
        local = -(double)logf(a + 1e-12f) * (double)bows[(size_t)b * V_ + v];
    }
    red[tid] = local; __syncthreads();
    for (int st = 128; st > 0; st >>= 1) { if (tid < st) red[tid] += red[tid + st]; __syncthreads(); }
    if (tid == 0) atomicAdd(&acc[0], red[0]);
}

// ---------------- alpha KL ----------------
__global__ __launch_bounds__(256) void k_alpha(const float* __restrict__ mua,
                                               const float* __restrict__ lsa, double* acc)
{
    __shared__ double red[256];
    const float LOGD = (float)log(0.005);
    const float DEN1 = 1.0f + 1e-6f;
    const float DEND = __fadd_rn(exp_acc(LOGD), 1e-6f);
    int tid = threadIdx.x;
    double local = 0.0;
    int tot = K_ * T_ * R_;
    for (int idx = blockIdx.x * 256 + tid; idx < tot; idx += gridDim.x * 256) {
        int t = (idx / R_) % T_;
        float mu = mua[idx], ls = lsa[idx];
        float pmu = (t == 0) ? 0.f : mua[idx - R_];
        float pls = (t == 0) ? 0.f : LOGD;
        float den = (t == 0) ? DEN1 : DEND;
        float d  = __fadd_rn(mu, -pmu);
        float d2 = __fmul_rn(d, d);
        float Ex = expf(ls);
        float S  = __fadd_rn(Ex, d2);
        float Q  = __fdiv_rn(S, den);
        float t1 = __fadd_rn(Q, -1.0f);
        float t2 = __fadd_rn(t1, pls);
        local += (double)__fadd_rn(t2, -ls);
    }
    red[tid] = local; __syncthreads();
    for (int st = 128; st > 0; st >>= 1) { if (tid < st) red[tid] += red[tid + st]; __syncthreads(); }
    if (tid == 0) atomicAdd(&acc[3], 0.5 * red[0]);
}

// ---------------- finalize ----------------
__global__ void k_final(float* out, const double* acc) {
    if (threadIdx.x == 0 && blockIdx.x == 0) {
        double nll = acc[0] * COEFF;
        double kle = acc[1];
        double klt = acc[2] * COEFF;
        double kla = acc[3];
        out[0] = (float)(nll + kle + klt + kla);
        out[1] = (float)nll;
        out[2] = (float)kle;
        out[3] = (float)klt;
        out[4] = (float)kla;
    }
}

// ---------------- launch ----------------
extern "C" void kernel_launch(void* const* d_in, const int* in_sizes, int n_in,
                              void* d_out, int out_size)
{
    const float* bows = (const float*)d_in[0];
    const int*   times = (const int*)d_in[1];
    const float* rnn  = (const float*)d_in[2];
    const float* rho  = (const float*)d_in[3];
    const float* mua  = (const float*)d_in[4];
    const float* lsa  = (const float*)d_in[5];
    const float* qW1  = (const float*)d_in[6];
    const float* qb1  = (const float*)d_in[7];
    const float* qW2  = (const float*)d_in[8];
    const float* qb2  = (const float*)d_in[9];
    const float* mtW  = (const float*)d_in[10];
    const float* mtb  = (const float*)d_in[11];
    const float* ltW  = (const float*)d_in[12];
    const float* ltb  = (const float*)d_in[13];
    const float* emW  = (const float*)d_in[14];
    const float* emb  = (const float*)d_in[15];
    const float* Wih  = (const float*)d_in[16];
    const float* Whh  = (const float*)d_in[17];
    const float* bih  = (const float*)d_in[18];
    const float* bhh  = (const float*)d_in[19];
    const float* meW  = (const float*)d_in[20];
    const float* meb  = (const float*)d_in[21];
    const float* leW  = (const float*)d_in[22];
    const float* leb  = (const float*)d_in[23];
    float* out = (float*)d_out;

    float *E, *Z, *X, *etas, *enc, *h1, *h2, *w, *w1p, *part;
    __nv_bfloat16 *aTh, *rhh;
    double* acc;
    cudaGetSymbolAddress((void**)&E, g_E);
    cudaGetSymbolAddress((void**)&Z, g_Z);
    cudaGetSymbolAddress((void**)&X, g_x);
    cudaGetSymbolAddress((void**)&etas, g_etas);
    cudaGetSymbolAddress((void**)&enc, g_enc);
    cudaGetSymbolAddress((void**)&h1, g_h1);
    cudaGetSymbolAddress((void**)&h2, g_h2);
    cudaGetSymbolAddress((void**)&w, g_w);
    cudaGetSymbolAddress((void**)&w1p, g_w1p);
    cudaGetSymbolAddress((void**)&part, g_part);
    cudaGetSymbolAddress((void**)&aTh, g_aTh);
    cudaGetSymbolAddress((void**)&rhh, g_rhh);
    cudaGetSymbolAddress((void**)&acc, g_acc);

    float* partEta = part + ETA_OFF;          // disjoint region for eta_map slabs
    float* partG1b = part + 63 * G1SLAB;      // 64th slab for the eta-column GEMM1 part

    cudaFuncSetAttribute(rec_pipeline, cudaFuncAttributeMaxDynamicSharedMemorySize, REC_SMEM);

    static cudaStream_t s2 = nullptr;
    static cudaEvent_t evA = nullptr, evB = nullptr, evC = nullptr;
    if (!s2) {
        cudaStreamCreateWithFlags(&s2, cudaStreamNonBlocking);
        cudaEventCreateWithFlags(&evA, cudaEventDisableTiming);
        cudaEventCreateWithFlags(&evB, cudaEventDisableTiming);
        cudaEventCreateWithFlags(&evC, cudaEventDisableTiming);
    }

    // ---- main chain ----
    k_init<<<256, 256>>>();
    cudaEventRecord(evA, 0);

    // eta_map: X = rnn @ emW.T + emb  (uses disjoint eta slab region)
    gemm_nt<<<dim3(2, 1, 105), 256>>>(rnn, emW, partEta, T_, H_, V_, V_, V_);
    k_red<<<79, 256>>>(X, partEta, emb, T_, H_, 105, 0);

    // fused 3-layer LSTM + eta pipeline  (launch #4 -> profiled)
    rec_pipeline<<<25, 256, REC_SMEM>>>(X, Wih, Whh, bih, bhh, meW, meb, leW, leb, etas, acc);

    // ---- side stream: w1p/enc + hidden GEMM1a, then beta + alpha ----
    cudaStreamWaitEvent(s2, evA, 0);
    k_prep_w1<<<1024, 256, 0, s2>>>(qW1);
    k_enc_bows<<<B_, 256, 0, s2>>>(bows, enc);
    // GEMM1a: bows-columns part of encoder GEMM1 (K=10000), hidden under rec
    gemm_nt<<<dim3(7, 1, 63), 256, 0, s2>>>(enc, w1p, part, B_, EN_, 10000, VKP_, VKP_);
    cudaEventRecord(evC, s2);
    k_prep_beta<<<2048, 256, 0, s2>>>(rho, mua);
    beta_mma<<<dim3(NP / 128, MP / 128), 256, 0, s2>>>(aTh, rhh, E, Z);
    k_alpha<<<768, 256, 0, s2>>>(mua, lsa, acc);
    cudaEventRecord(evB, s2);

    // ---- main chain continues after rec ----
    k_enc_eta<<<B_, 64>>>(times, etas, enc);
    // GEMM1b: eta-columns part (K=56) into slab 63
    gemm_nt<<<dim3(7, 1, 1), 256>>>(enc + V_, w1p + V_, partG1b, B_, EN_, 56, VKP_, VKP_);

    cudaStreamWaitEvent(0, evC, 0);
    k_red<<<400, 256>>>(h1, part, qb1, B_, EN_, 64, 1);
    gemm_nt<<<dim3(7, 1, 15), 256>>>(h1, qW2, part, B_, EN_, EN_, EN_, EN_);
    k_red<<<400, 256>>>(h2, part, qb2, B_, EN_, 15, 1);

    cudaStreamWaitEvent(0, evB, 0);
    k_theta<<<B_, 128>>>(h2, mtW, mtb, ltW, ltb, times, etas, Z, w, acc);
    k_nll<<<dim3((V_ + 255) / 256, B_), 256>>>(bows, times, w, E, acc);
    k_final<<<1, 1>>>(out, acc);
}